// round 15
// baseline (speedup 1.0000x reference)
#include <cuda_runtime.h>
#include <cuda_bf16.h>
#include <math.h>
#include <stdint.h>

#define BB 4
#define TT 16384
#define SSZ 8192
#define DD 256
#define GG 512
#define KX 259
#define MM (BB*TT)              /* 65536 rows */
#define NTILE (MM/128)          /* 512 row tiles */
#define KNN 8

#if defined(__CUDA_ARCH_FEAT_SM103_ALL) || defined(__CUDA_ARCH_FEAT_SM100_ALL) || \
    defined(__CUDA_ARCH_FEAT_SM101_ALL) || defined(__CUDA_ARCH_SPECIFIC__)
#define TC_ENABLED 1
#else
#define TC_ENABLED 0
#endif

// ---------------------------------------------------------------------------
// Static device scratch (x: cols 0..255 local, 256..258 tmpl, 259..319 pad=0)
// ---------------------------------------------------------------------------
__device__ __align__(16) __nv_bfloat16 g_xh [(size_t)NTILE * 5 * 8192];
__device__ __align__(16) __nv_bfloat16 g_xl [(size_t)NTILE * 5 * 8192];
__device__ __align__(16) __nv_bfloat16 g_h1h[(size_t)NTILE * 4 * 8192];
__device__ __align__(16) __nv_bfloat16 g_h1l[(size_t)NTILE * 4 * 8192];
__device__ __align__(16) __nv_bfloat16 g_m1h[(size_t)NTILE * 2 * 8192];
__device__ __align__(16) __nv_bfloat16 g_m1l[(size_t)NTILE * 2 * 8192];

__device__ __align__(16) __nv_bfloat16 g_dw1h[5 * 256 * 64], g_dw1l[5 * 256 * 64];
__device__ __align__(16) __nv_bfloat16 g_dw2h[4 * 256 * 64], g_dw2l[4 * 256 * 64];
__device__ __align__(16) __nv_bfloat16 g_mw1h[5 * 128 * 64], g_mw1l[5 * 128 * 64];
__device__ __align__(16) __nv_bfloat16 g_mw2h[2 * 64 * 64],  g_mw2l[2 * 64 * 64];

__device__ float g_gbd[4 * 256];
__device__ float g_gbm[4 * 128];

// ---------------------------------------------------------------------------
// PTX helpers
// ---------------------------------------------------------------------------
__device__ __forceinline__ uint32_t smem_u32(const void* p) {
    uint32_t a;
    asm("{ .reg .u64 t; cvta.to.shared.u64 t, %1; cvt.u32.u64 %0, t; }" : "=r"(a) : "l"(p));
    return a;
}
__device__ __forceinline__ uint32_t elect_one_pred() {
    uint32_t p;
    asm volatile("{ .reg .pred p; elect.sync _|p, 0xFFFFFFFF; selp.b32 %0, 1, 0, p; }" : "=r"(p));
    return p;
}
#define SWZ128(x) ((x) ^ (((x) >> 3) & 0x70))

static __device__ constexpr uint64_t SMEM_DESC_BASE_SW128 =
    (uint64_t(2) << 61) | (uint64_t(1) << 46) | (uint64_t(64) << 32) | (uint64_t(1) << 16);
#define MAKE_DESC(addr) (SMEM_DESC_BASE_SW128 | ((uint64_t)((addr) >> 4) & 0x3FFF))

#if TC_ENABLED
#define TC_ALLOC(sm, n)  asm volatile("tcgen05.alloc.cta_group::1.sync.aligned.shared::cta.b32 [%0], %1;" :: "r"((uint32_t)(sm)), "r"((uint32_t)(n)) : "memory")
#define TC_DEALLOC(t, n) asm volatile("tcgen05.dealloc.cta_group::1.sync.aligned.b32 %0, %1;" :: "r"(t), "r"((uint32_t)(n)))
#define TC_RELINQ()      asm volatile("tcgen05.relinquish_alloc_permit.cta_group::1.sync.aligned;")
#define TC_COMMIT(mb)    asm volatile("tcgen05.commit.cta_group::1.mbarrier::arrive::one.shared::cluster.b64 [%0];" :: "r"((uint32_t)(mb)) : "memory")
#define TC_FENCE_AFTER() asm volatile("tcgen05.fence::after_thread_sync;" ::: "memory")
#define TC_WAIT_LD()     asm volatile("tcgen05.wait::ld.sync.aligned;" ::: "memory")
#else
#define TC_ALLOC(sm, n)
#define TC_DEALLOC(t, n)
#define TC_RELINQ()
#define TC_COMMIT(mb)
#define TC_FENCE_AFTER()
#define TC_WAIT_LD()
#endif

#define MBAR_INIT(mb, c) asm volatile("mbarrier.init.shared.b64 [%0], %1;" :: "r"((uint32_t)(mb)), "r"((uint32_t)(c)) : "memory")
#define MBAR_EXPECT_TX(mb, n) asm volatile("mbarrier.arrive.expect_tx.shared.b64 _, [%0], %1;" :: "r"((uint32_t)(mb)), "r"((uint32_t)(n)) : "memory")
#define BULK_G2S(dst, src, bytes, mb) \
    asm volatile("cp.async.bulk.shared::cluster.global.mbarrier::complete_tx::bytes [%0], [%1], %2, [%3];" \
        :: "r"((uint32_t)(dst)), "l"(src), "r"((uint32_t)(bytes)), "r"((uint32_t)(mb)) : "memory")
#define BULK_S2G(gdst, ssrc, bytes) \
    asm volatile("cp.async.bulk.global.shared::cta.bulk_group [%0], [%1], %2;" \
        :: "l"(gdst), "r"((uint32_t)(ssrc)), "r"((uint32_t)(bytes)) : "memory")
#define FENCE_ASYNC() asm volatile("fence.proxy.async.shared::cta;" ::: "memory")

__device__ __forceinline__ void mbar_wait(uint32_t mb, uint32_t parity) {
    uint32_t done;
    asm volatile(
        "{ .reg .pred p; mbarrier.try_wait.parity.acquire.cta.shared::cta.b64 p, [%1], %2; selp.b32 %0, 1, 0, p; }"
        : "=r"(done) : "r"(mb), "r"(parity) : "memory");
    if (!done) {
        asm volatile(
            "{ .reg .pred P1;\n"
            "W%=: mbarrier.try_wait.parity.acquire.cta.shared::cta.b64 P1, [%0], %1, 0x989680;\n"
            "@P1 bra.uni D%=;\n bra.uni W%=;\n D%=: }"
            :: "r"(mb), "r"(parity) : "memory");
    }
}

__device__ __forceinline__ void mma_f16_ss(uint32_t d, uint64_t a, uint64_t b,
                                           uint32_t idesc, uint32_t en) {
#if TC_ENABLED
    asm volatile(
        "{ .reg .pred p; setp.ne.u32 p, %4, 0;\n"
        "tcgen05.mma.cta_group::1.kind::f16 [%0], %1, %2, %3, {%5,%5,%5,%5}, p; }"
        :: "r"(d), "l"(a), "l"(b), "r"(idesc), "r"(en), "r"(0u) : "memory");
#endif
}

__device__ __forceinline__ void tc_ld_x32(uint32_t* r, uint32_t addr) {
#if TC_ENABLED
    asm volatile("tcgen05.ld.sync.aligned.32x32b.x32.b32 "
        "{%0,%1,%2,%3,%4,%5,%6,%7,%8,%9,%10,%11,%12,%13,%14,%15,"
        "%16,%17,%18,%19,%20,%21,%22,%23,%24,%25,%26,%27,%28,%29,%30,%31}, [%32];"
        : "=r"(r[0]),"=r"(r[1]),"=r"(r[2]),"=r"(r[3]),"=r"(r[4]),"=r"(r[5]),"=r"(r[6]),"=r"(r[7]),
          "=r"(r[8]),"=r"(r[9]),"=r"(r[10]),"=r"(r[11]),"=r"(r[12]),"=r"(r[13]),"=r"(r[14]),"=r"(r[15]),
          "=r"(r[16]),"=r"(r[17]),"=r"(r[18]),"=r"(r[19]),"=r"(r[20]),"=r"(r[21]),"=r"(r[22]),"=r"(r[23]),
          "=r"(r[24]),"=r"(r[25]),"=r"(r[26]),"=r"(r[27]),"=r"(r[28]),"=r"(r[29]),"=r"(r[30]),"=r"(r[31])
        : "r"(addr));
#endif
}

// ---------------------------------------------------------------------------
// Kernel 1: KNN (k=8), 2 threads/point, min-of-4 batched scan, smem merge,
// gather/mean + direct packed x emission. blk0 = block offset (split launch).
// ---------------------------------------------------------------------------
#define PPB 256
#define NTH 512
#define SCH 2048

__device__ __forceinline__ void heap_insert(
    float d2, int idx, float bd[KNN], int bi[KNN], float& wmax, int& wslot)
{
#pragma unroll
    for (int i = 0; i < KNN; i++)
        if (i == wslot) { bd[i] = d2; bi[i] = idx; }
    float wm = -3.4e38f; int ws = 0;
#pragma unroll
    for (int i = 0; i < KNN; i++)
        if (bd[i] > wm) { wm = bd[i]; ws = i; }
    wmax = wm; wslot = ws;
}

__global__ void __launch_bounds__(NTH) knn_build_xpk(
    const float* __restrict__ tmpl, const float* __restrict__ surf,
    const float* __restrict__ pfeat, int blk0)
{
    __shared__ float4 ssurf[SCH];
    __shared__ int    sidx[PPB * KNN];
    __shared__ float  sdB[PPB * KNN];
    __shared__ int    siB[PPB * KNN];

    const int blk = blockIdx.x + blk0;
    const int b  = blk / (TT / PPB);
    const int p0 = (blk % (TT / PPB)) * PPB;
    const int tid = threadIdx.x;
    const int pl  = tid & (PPB - 1);
    const int half = tid >> 8;

    const int pt = p0 + pl;
    const size_t trow = ((size_t)b * TT + pt) * 3;
    const float tx = tmpl[trow + 0], ty = tmpl[trow + 1], tz = tmpl[trow + 2];
    const float tsq = tx * tx + ty * ty + tz * tz;
    const float ntx = -2.f * tx, nty = -2.f * ty, ntz = -2.f * tz;

    float bd[KNN]; int bi[KNN];
#pragma unroll
    for (int i = 0; i < KNN; i++) { bd[i] = 3.4e38f; bi[i] = 0; }
    float wmax = 3.4e38f; int wslot = 0;

    for (int c0 = 0; c0 < SSZ; c0 += SCH) {
        __syncthreads();
        for (int i = tid; i < SCH; i += NTH) {
            size_t srow = ((size_t)b * SSZ + c0 + i) * 3;
            float sx = surf[srow], sy = surf[srow + 1], sz = surf[srow + 2];
            ssurf[i] = make_float4(sx, sy, sz, sx * sx + sy * sy + sz * sz);
        }
        __syncthreads();
        const int sbeg = half * (SCH / 2);
        for (int s = sbeg; s < sbeg + SCH / 2; s += 4) {
            float4 v0 = ssurf[s + 0], v1 = ssurf[s + 1];
            float4 v2 = ssurf[s + 2], v3 = ssurf[s + 3];
            float e0 = fmaf(ntx, v0.x, fmaf(nty, v0.y, fmaf(ntz, v0.z, tsq + v0.w)));
            float e1 = fmaf(ntx, v1.x, fmaf(nty, v1.y, fmaf(ntz, v1.z, tsq + v1.w)));
            float e2 = fmaf(ntx, v2.x, fmaf(nty, v2.y, fmaf(ntz, v2.z, tsq + v2.w)));
            float e3 = fmaf(ntx, v3.x, fmaf(nty, v3.y, fmaf(ntz, v3.z, tsq + v3.w)));
            float m = fminf(fminf(e0, e1), fminf(e2, e3));
            if (m < wmax) {
                if (e0 < wmax) heap_insert(e0, c0 + s + 0, bd, bi, wmax, wslot);
                if (e1 < wmax) heap_insert(e1, c0 + s + 1, bd, bi, wmax, wslot);
                if (e2 < wmax) heap_insert(e2, c0 + s + 2, bd, bi, wmax, wslot);
                if (e3 < wmax) heap_insert(e3, c0 + s + 3, bd, bi, wmax, wslot);
            }
        }
    }

    if (half == 1) {
#pragma unroll
        for (int i = 0; i < KNN; i++) {
            sdB[pl * KNN + i] = bd[i];
            siB[pl * KNN + i] = bi[i];
        }
    }
    __syncthreads();
    if (half == 0) {
#pragma unroll
        for (int n = 0; n < KNN; n++) {
            float d2 = sdB[pl * KNN + n];
            int   ii = siB[pl * KNN + n];
            if (d2 < wmax) heap_insert(d2, ii, bd, bi, wmax, wslot);
        }
#pragma unroll
        for (int i = 0; i < KNN; i++) sidx[pl * KNN + i] = bi[i];
    }
    __syncthreads();

    const int lane = tid & 31, wid = tid >> 5;
    for (int q = 0; q < PPB / 16; q++) {
        const int lp = wid * (PPB / 16) + q;
        float acc[8];
#pragma unroll
        for (int j = 0; j < 8; j++) acc[j] = 0.f;
#pragma unroll
        for (int n = 0; n < KNN; n++) {
            const int sI = sidx[lp * KNN + n];
            const float4* rowp = (const float4*)(pfeat + ((size_t)b * SSZ + sI) * DD + lane * 8);
            float4 a0 = rowp[0], a1 = rowp[1];
            acc[0] += a0.x; acc[1] += a0.y; acc[2] += a0.z; acc[3] += a0.w;
            acc[4] += a1.x; acc[5] += a1.y; acc[6] += a1.z; acc[7] += a1.w;
        }
        const int row = b * TT + p0 + lp;
        const int tile = row >> 7, rloc = row & 127;
        __align__(16) __nv_bfloat16 h[8], l[8];
#pragma unroll
        for (int j = 0; j < 8; j++) {
            float v = acc[j] * 0.125f;
            h[j] = __float2bfloat16(v);
            l[j] = __float2bfloat16(v - __bfloat162float(h[j]));
        }
        const uint32_t off = SWZ128((uint32_t)(rloc * 128 + ((lane & 7) << 4)));
        const size_t blkb = ((size_t)(tile * 5) + (lane >> 3)) * 16384 + off;
        *(uint4*)((char*)g_xh + blkb) = *(const uint4*)h;
        *(uint4*)((char*)g_xl + blkb) = *(const uint4*)l;
        if (lane < 3) {
            float v = tmpl[(size_t)row * 3 + lane];
            __nv_bfloat16 hh = __float2bfloat16(v);
            __nv_bfloat16 ll = __float2bfloat16(v - __bfloat162float(hh));
            const uint32_t o2 = SWZ128((uint32_t)(rloc * 128)) + (lane << 1);
            const size_t b2 = ((size_t)(tile * 5) + 4) * 16384 + o2;
            *(__nv_bfloat16*)((char*)g_xh + b2) = hh;
            *(__nv_bfloat16*)((char*)g_xl + b2) = ll;
        }
    }
}

// ---------------------------------------------------------------------------
// prep jobs (layer-1 weights use permuted row map: k'<256 -> k'+3; 256..258 -> k'-256)
// ---------------------------------------------------------------------------
__device__ __forceinline__ void pack_w1_elem(
    const float* W, __nv_bfloat16* hi, __nv_bfloat16* lo, int idx, int N)
{
    int n = idx / 320, kp = idx - n * 320;
    float v;
    if (kp < 256)       v = W[(size_t)(kp + 3) * N + n];
    else if (kp < 259)  v = W[(size_t)(kp - 256) * N + n];
    else                v = 0.f;
    __nv_bfloat16 h = __float2bfloat16(v);
    int ch = kp >> 6, kc = kp & 63;
    uint32_t e = (uint32_t)ch * (N * 64) + (SWZ128((uint32_t)(n * 128 + kc * 2)) >> 1);
    hi[e] = h;
    lo[e] = __float2bfloat16(v - __bfloat162float(h));
}

__device__ __forceinline__ void pack_w_elem(
    const float* W, __nv_bfloat16* hi, __nv_bfloat16* lo,
    int idx, int N, int Kpad)
{
    int n = idx / Kpad, k = idx - n * Kpad;
    float v = W[(size_t)k * N + n];
    __nv_bfloat16 h = __float2bfloat16(v);
    int ch = k >> 6, kc = k & 63;
    uint32_t e = (uint32_t)ch * (N * 64) + (SWZ128((uint32_t)(n * 128 + kc * 2)) >> 1);
    hi[e] = h;
    lo[e] = __float2bfloat16(v - __bfloat162float(h));
}

__global__ void __launch_bounds__(256) prep_job(
    int job,
    const float* __restrict__ W, const float* __restrict__ bias_in,
    const float* __restrict__ gfeat)
{
    const int bid = blockIdx.x, tid = threadIdx.x;
    if (job == 0) {
        pack_w1_elem(W, g_dw1h, g_dw1l, bid * 256 + tid, 256);
    } else if (job == 1) {
        pack_w_elem(W, g_dw2h, g_dw2l, bid * 256 + tid, 256, 256);
    } else if (job == 2) {
        pack_w1_elem(W, g_mw1h, g_mw1l, bid * 256 + tid, 128);
    } else if (job == 3) {
        pack_w_elem(W, g_mw2h, g_mw2l, bid * 256 + tid, 64, 128);
    } else {
        int b = bid;
        float s = bias_in[tid];
#pragma unroll 4
        for (int k = 0; k < GG; k++)
            s = fmaf(gfeat[b * GG + k], W[(size_t)(KX + k) * 256 + tid], s);
        g_gbd[b * 256 + tid] = s;
    }
}

__global__ void __launch_bounds__(256) prep_gbm(
    const float* __restrict__ mw1, const float* __restrict__ mb1,
    const float* __restrict__ gfeat)
{
    const int b = blockIdx.x, tid = threadIdx.x;
    if (tid < 128) {
        float s = mb1[tid];
#pragma unroll 4
        for (int k = 0; k < GG; k++)
            s = fmaf(gfeat[b * GG + k], mw1[(size_t)(KX + k) * 128 + tid], s);
        g_gbm[b * 128 + tid] = s;
    }
}

// ---------------------------------------------------------------------------
// tcgen05 GEMM with fused epilogue; tile0 = tile offset for half-launches.
// ---------------------------------------------------------------------------
#define OUT_PACK 0
#define OUT_DISP 1
#define OUT_MAT  2

template<int NT, int OMODE>
__global__ void __launch_bounds__(128) gemm_tc3(
    const __nv_bfloat16* __restrict__ Ah, const __nv_bfloat16* __restrict__ Al, int nch,
    const __nv_bfloat16* __restrict__ Bh, const __nv_bfloat16* __restrict__ Bl,
    const float* __restrict__ bias, int bstride,
    __nv_bfloat16* __restrict__ Oh, __nv_bfloat16* __restrict__ Ol,
    const float* __restrict__ w3, const float* __restrict__ b3,
    float* __restrict__ out, int tile0)
{
#if TC_ENABLED
    extern __shared__ __align__(1024) char smem[];
    constexpr uint32_t B_OFF = 32768u;
    constexpr uint32_t STAGE = 32768u + NT * 256u;
    constexpr int SWN = (OMODE == OUT_DISP) ? 768 : ((OMODE == OUT_MAT) ? 64 : 1);
    __shared__ uint32_t s_tmem;
    __shared__ __align__(8) uint64_t s_mb[4];
    __shared__ float sb[NT];
    __shared__ float sw[SWN];

    const uint32_t smb  = smem_u32(smem);
    const uint32_t mbb  = smem_u32(&s_mb[0]);
    const int tid = threadIdx.x, wid = tid >> 5, lane = tid & 31;
    const int tile = blockIdx.x + tile0, bm = tile * 128;

    for (int i = tid; i < NT; i += 128) sb[i] = bias[(bm >> 14) * bstride + i];
    if (OMODE != OUT_PACK)
        for (int i = tid; i < SWN; i += 128) sw[i] = w3[i];
    if (wid == 0) { TC_ALLOC(smem_u32(&s_tmem), NT); TC_RELINQ(); }
    if (tid == 0)
        for (int i = 0; i < 4; i++) MBAR_INIT(mbb + i * 8, 1);
    __syncthreads();
    uint32_t tmem;
    asm volatile("ld.shared.b32 %0, [%1];" : "=r"(tmem) : "r"(smem_u32(&s_tmem)));

    const uint32_t idesc = (1u << 4) | (1u << 7) | (1u << 10) | ((NT / 8) << 17) | (8u << 24);

    if (wid == 0) {
        uint32_t pd[2] = {0u, 0u}, pm[2] = {0u, 0u};
        const uint32_t ep = elect_one_pred();

        if (ep) {
            for (int c = 0; c < 2 && c < nch; c++) {
                const int s = c & 1;
                const uint32_t st = smb + s * STAGE;
                MBAR_EXPECT_TX(mbb + s * 8, STAGE);
                BULK_G2S(st,                    Ah + ((size_t)tile * nch + c) * 8192, 16384, mbb + s * 8);
                BULK_G2S(st + 16384,            Al + ((size_t)tile * nch + c) * 8192, 16384, mbb + s * 8);
                BULK_G2S(st + B_OFF,            Bh + (size_t)c * NT * 64, NT * 128, mbb + s * 8);
                BULK_G2S(st + B_OFF + NT * 128, Bl + (size_t)c * NT * 64, NT * 128, mbb + s * 8);
            }
        }
        for (int ch = 0; ch < nch; ch++) {
            const int s = ch & 1;
            const uint32_t st = smb + s * STAGE;
            mbar_wait(mbb + s * 8, pd[s]); pd[s] ^= 1;
            if (ep) {
                uint64_t ah = MAKE_DESC(st), al = MAKE_DESC(st + 16384);
                uint64_t bh = MAKE_DESC(st + B_OFF), bl = MAKE_DESC(st + B_OFF + NT * 128);
#pragma unroll
                for (int ks = 0; ks < 4; ks++) {
                    uint32_t en0 = (ch == 0 && ks == 0) ? 0u : 1u;
                    mma_f16_ss(tmem, ah + ks * 2, bh + ks * 2, idesc, en0);
                    mma_f16_ss(tmem, ah + ks * 2, bl + ks * 2, idesc, 1u);
                    mma_f16_ss(tmem, al + ks * 2, bh + ks * 2, idesc, 1u);
                }
                TC_COMMIT(mbb + 16 + s * 8);
            }
            if (ch + 2 < nch) {
                mbar_wait(mbb + 16 + s * 8, pm[s]); pm[s] ^= 1;
                if (ep) {
                    const int c = ch + 2;
                    MBAR_EXPECT_TX(mbb + s * 8, STAGE);
                    BULK_G2S(st,                    Ah + ((size_t)tile * nch + c) * 8192, 16384, mbb + s * 8);
                    BULK_G2S(st + 16384,            Al + ((size_t)tile * nch + c) * 8192, 16384, mbb + s * 8);
                    BULK_G2S(st + B_OFF,            Bh + (size_t)c * NT * 64, NT * 128, mbb + s * 8);
                    BULK_G2S(st + B_OFF + NT * 128, Bl + (size_t)c * NT * 64, NT * 128, mbb + s * 8);
                }
            }
        }
        const int fs = (nch - 1) & 1;
        mbar_wait(mbb + 16 + fs * 8, pm[fs]);
    }
    __syncthreads();
    TC_FENCE_AFTER();

    const int rloc = wid * 32 + lane;
    const size_t row = (size_t)bm + rloc;

    if (OMODE == OUT_PACK) {
        constexpr int NCH2 = NT / 64;
#pragma unroll
        for (int c0 = 0; c0 < NT; c0 += 32) {
            uint32_t r[32];
            tc_ld_x32(r, tmem + c0);
            TC_WAIT_LD();
#pragma unroll
            for (int j4 = 0; j4 < 8; j4++) {
                const int c = c0 + j4 * 4;
                float v0 = fmaxf(__uint_as_float(r[j4 * 4 + 0]) + sb[c + 0], 0.f);
                float v1 = fmaxf(__uint_as_float(r[j4 * 4 + 1]) + sb[c + 1], 0.f);
                float v2 = fmaxf(__uint_as_float(r[j4 * 4 + 2]) + sb[c + 2], 0.f);
                float v3 = fmaxf(__uint_as_float(r[j4 * 4 + 3]) + sb[c + 3], 0.f);
                __align__(8) __nv_bfloat16 hh[4], ll[4];
                hh[0] = __float2bfloat16(v0); ll[0] = __float2bfloat16(v0 - __bfloat162float(hh[0]));
                hh[1] = __float2bfloat16(v1); ll[1] = __float2bfloat16(v1 - __bfloat162float(hh[1]));
                hh[2] = __float2bfloat16(v2); ll[2] = __float2bfloat16(v2 - __bfloat162float(hh[2]));
                hh[3] = __float2bfloat16(v3); ll[3] = __float2bfloat16(v3 - __bfloat162float(hh[3]));
                const int chunk = c >> 6, cc = c & 63;
                uint32_t off = (uint32_t)chunk * 16384u
                             + SWZ128((uint32_t)(rloc * 128 + ((cc >> 3) << 4)))
                             + (uint32_t)((cc & 7) << 1);
                *(uint64_t*)(smem + off)                   = *(const uint64_t*)hh;
                *(uint64_t*)(smem + NCH2 * 16384u + off)   = *(const uint64_t*)ll;
            }
        }
        __syncthreads();
        if (tid == 0) {
            FENCE_ASYNC();
            for (int ch = 0; ch < NCH2; ch++) {
                BULK_S2G(Oh + ((size_t)tile * NCH2 + ch) * 8192, smb + ch * 16384u, 16384);
                BULK_S2G(Ol + ((size_t)tile * NCH2 + ch) * 8192, smb + (NCH2 + ch) * 16384u, 16384);
            }
            asm volatile("cp.async.bulk.commit_group;" ::: "memory");
            asm volatile("cp.async.bulk.wait_group 0;" ::: "memory");
        }
    } else {
        float a0 = 0.f, a1 = 0.f, a2 = 0.f;
#pragma unroll
        for (int c0 = 0; c0 < NT; c0 += 32) {
            uint32_t r[32];
            tc_ld_x32(r, tmem + c0);
            TC_WAIT_LD();
#pragma unroll
            for (int j4 = 0; j4 < 8; j4++) {
                const int c = c0 + j4 * 4;
#pragma unroll
                for (int k = 0; k < 4; k++) {
                    float v = fmaxf(__uint_as_float(r[j4 * 4 + k]) + sb[c + k], 0.f);
                    if (OMODE == OUT_DISP) {
                        a0 = fmaf(v, sw[(c + k) * 3 + 0], a0);
                        a1 = fmaf(v, sw[(c + k) * 3 + 1], a1);
                        a2 = fmaf(v, sw[(c + k) * 3 + 2], a2);
                    } else {
                        a0 = fmaf(v, sw[c + k], a0);
                    }
                }
            }
        }
        if (OMODE == OUT_DISP) {
            out[row * 3 + 0] = a0 + b3[0];
            out[row * 3 + 1] = a1 + b3[1];
            out[row * 3 + 2] = a2 + b3[2];
        } else {
            float z = a0 + b3[0];
            out[row] = 1.f / (1.f + expf(-z));
        }
    }
    __syncthreads();
    if (wid == 0) TC_DEALLOC(tmem, NT);
#endif  // TC_ENABLED
}

// ---------------------------------------------------------------------------
extern "C" void kernel_launch(void* const* d_in, const int* in_sizes, int n_in,
                              void* d_out, int out_size)
{
    const float* tmpl  = (const float*)d_in[0];
    const float* surf  = (const float*)d_in[1];
    const float* gfeat = (const float*)d_in[2];
    const float* pfeat = (const float*)d_in[3];
    const float* dw1 = (const float*)d_in[4];
    const float* db1 = (const float*)d_in[5];
    const float* dw2 = (const float*)d_in[6];
    const float* db2 = (const float*)d_in[7];
    const float* dw3 = (const float*)d_in[8];
    const float* db3 = (const float*)d_in[9];
    const float* mw1 = (const float*)d_in[10];
    const float* mb1 = (const float*)d_in[11];
    const float* mw2 = (const float*)d_in[12];
    const float* mb2 = (const float*)d_in[13];
    const float* mw3 = (const float*)d_in[14];
    const float* mb3 = (const float*)d_in[15];
    float* out = (float*)d_out;

    float *gbd, *gbm;
    cudaGetSymbolAddress((void**)&gbd, g_gbd);
    cudaGetSymbolAddress((void**)&gbm, g_gbm);
    __nv_bfloat16 *xh, *xl, *h1h, *h1l, *m1h, *m1l;
    __nv_bfloat16 *dw1h, *dw1l, *dw2h, *dw2l, *mw1h, *mw1l, *mw2h, *mw2l;
    cudaGetSymbolAddress((void**)&xh,  g_xh);
    cudaGetSymbolAddress((void**)&xl,  g_xl);
    cudaGetSymbolAddress((void**)&h1h, g_h1h);
    cudaGetSymbolAddress((void**)&h1l, g_h1l);
    cudaGetSymbolAddress((void**)&m1h, g_m1h);
    cudaGetSymbolAddress((void**)&m1l, g_m1l);
    cudaGetSymbolAddress((void**)&dw1h, g_dw1h);
    cudaGetSymbolAddress((void**)&dw1l, g_dw1l);
    cudaGetSymbolAddress((void**)&dw2h, g_dw2h);
    cudaGetSymbolAddress((void**)&dw2l, g_dw2l);
    cudaGetSymbolAddress((void**)&mw1h, g_mw1h);
    cudaGetSymbolAddress((void**)&mw1l, g_mw1l);
    cudaGetSymbolAddress((void**)&mw2h, g_mw2h);
    cudaGetSymbolAddress((void**)&mw2l, g_mw2l);

    const int SM1 = 2 * (32768 + 256 * 256);
    const int SM3 = 2 * (32768 + 128 * 256);
    const int SM4 = 2 * (32768 +  64 * 256);
    cudaFuncSetAttribute((const void*)gemm_tc3<256, OUT_PACK>, cudaFuncAttributeMaxDynamicSharedMemorySize, SM1);
    cudaFuncSetAttribute((const void*)gemm_tc3<256, OUT_DISP>, cudaFuncAttributeMaxDynamicSharedMemorySize, SM1);
    cudaFuncSetAttribute((const void*)gemm_tc3<128, OUT_PACK>, cudaFuncAttributeMaxDynamicSharedMemorySize, SM3);
    cudaFuncSetAttribute((const void*)gemm_tc3<64,  OUT_MAT>,  cudaFuncAttributeMaxDynamicSharedMemorySize, SM4);

    static cudaStream_t s1 = nullptr, s2 = nullptr;
    static cudaEvent_t ev0 = nullptr, evP = nullptr, evXA = nullptr, evXB = nullptr,
                       evD = nullptr, evM = nullptr;
    static int forked = -1;
    if (forked < 0) {
        bool ok = cudaStreamCreateWithFlags(&s1, cudaStreamNonBlocking) == cudaSuccess
               && cudaStreamCreateWithFlags(&s2, cudaStreamNonBlocking) == cudaSuccess
               && cudaEventCreateWithFlags(&ev0, cudaEventDisableTiming) == cudaSuccess
               && cudaEventCreateWithFlags(&evP, cudaEventDisableTiming) == cudaSuccess
               && cudaEventCreateWithFlags(&evXA, cudaEventDisableTiming) == cudaSuccess
               && cudaEventCreateWithFlags(&evXB, cudaEventDisableTiming) == cudaSuccess
               && cudaEventCreateWithFlags(&evD, cudaEventDisableTiming) == cudaSuccess
               && cudaEventCreateWithFlags(&evM, cudaEventDisableTiming) == cudaSuccess;
        forked = ok ? 1 : 0;
    }

    const int HB = (MM / PPB) / 2;      // 128 blocks per half
    const int HT = NTILE / 2;           // 256 tiles per half

    if (forked == 1) {
        cudaEventRecord(ev0, 0);
        cudaStreamWaitEvent(s1, ev0, 0);
        prep_job<<<320, 256, 0, s1>>>(0, dw1, nullptr, gfeat);
        prep_job<<<256, 256, 0, s1>>>(1, dw2, nullptr, gfeat);
        prep_job<<<160, 256, 0, s1>>>(2, mw1, nullptr, gfeat);
        prep_job<<<32,  256, 0, s1>>>(3, mw2, nullptr, gfeat);
        prep_job<<<4,   256, 0, s1>>>(4, dw1, db1, gfeat);
        prep_gbm<<<4,   256, 0, s1>>>(mw1, mb1, gfeat);
        cudaEventRecord(evP, s1);

        knn_build_xpk<<<HB, NTH>>>(tmpl, surf, pfeat, 0);      // batches 0,1
        cudaEventRecord(evXA, 0);
        knn_build_xpk<<<HB, NTH>>>(tmpl, surf, pfeat, HB);     // batches 2,3
        cudaEventRecord(evXB, 0);

        // disp chain on s2 (first half overlaps knnB)
        cudaStreamWaitEvent(s2, evXA, 0);
        cudaStreamWaitEvent(s2, evP, 0);
        gemm_tc3<256, OUT_PACK><<<HT, 128, SM1, s2>>>(
            xh, xl, 5, dw1h, dw1l, gbd, 256, h1h, h1l, nullptr, nullptr, nullptr, 0);
        gemm_tc3<256, OUT_DISP><<<HT, 128, SM1, s2>>>(
            h1h, h1l, 4, dw2h, dw2l, db2, 0, nullptr, nullptr, dw3, db3, out, 0);
        cudaStreamWaitEvent(s2, evXB, 0);
        gemm_tc3<256, OUT_PACK><<<HT, 128, SM1, s2>>>(
            xh, xl, 5, dw1h, dw1l, gbd, 256, h1h, h1l, nullptr, nullptr, nullptr, HT);
        gemm_tc3<256, OUT_DISP><<<HT, 128, SM1, s2>>>(
            h1h, h1l, 4, dw2h, dw2l, db2, 0, nullptr, nullptr, dw3, db3, out, HT);
        cudaEventRecord(evD, s2);

        // mat chain on s1
        cudaStreamWaitEvent(s1, evXA, 0);
        gemm_tc3<128, OUT_PACK><<<HT, 128, SM3, s1>>>(
            xh, xl, 5, mw1h, mw1l, gbm, 128, m1h, m1l, nullptr, nullptr, nullptr, 0);
        gemm_tc3<64, OUT_MAT><<<HT, 128, SM4, s1>>>(
            m1h, m1l, 2, mw2h, mw2l, mb2, 0, nullptr, nullptr, mw3, mb3, out + (size_t)MM * 3, 0);
        cudaStreamWaitEvent(s1, evXB, 0);
        gemm_tc3<128, OUT_PACK><<<HT, 128, SM3, s1>>>(
            xh, xl, 5, mw1h, mw1l, gbm, 128, m1h, m1l, nullptr, nullptr, nullptr, HT);
        gemm_tc3<64, OUT_MAT><<<HT, 128, SM4, s1>>>(
            m1h, m1l, 2, mw2h, mw2l, mb2, 0, nullptr, nullptr, mw3, mb3, out + (size_t)MM * 3, HT);
        cudaEventRecord(evM, s1);

        cudaStreamWaitEvent(0, evD, 0);
        cudaStreamWaitEvent(0, evM, 0);
    } else {
        prep_job<<<320, 256>>>(0, dw1, nullptr, gfeat);
        prep_job<<<256, 256>>>(1, dw2, nullptr, gfeat);
        prep_job<<<160, 256>>>(2, mw1, nullptr, gfeat);
        prep_job<<<32,  256>>>(3, mw2, nullptr, gfeat);
        prep_job<<<4,   256>>>(4, dw1, db1, gfeat);
        prep_gbm<<<4,   256>>>(mw1, mb1, gfeat);
        knn_build_xpk<<<HB, NTH>>>(tmpl, surf, pfeat, 0);
        knn_build_xpk<<<HB, NTH>>>(tmpl, surf, pfeat, HB);
        gemm_tc3<256, OUT_PACK><<<NTILE, 128, SM1>>>(
            xh, xl, 5, dw1h, dw1l, gbd, 256, h1h, h1l, nullptr, nullptr, nullptr, 0);
        gemm_tc3<128, OUT_PACK><<<NTILE, 128, SM3>>>(
            xh, xl, 5, mw1h, mw1l, gbm, 128, m1h, m1l, nullptr, nullptr, nullptr, 0);
        gemm_tc3<256, OUT_DISP><<<NTILE, 128, SM1>>>(
            h1h, h1l, 4, dw2h, dw2l, db2, 0, nullptr, nullptr, dw3, db3, out, 0);
        gemm_tc3<64, OUT_MAT><<<NTILE, 128, SM4>>>(
            m1h, m1l, 2, mw2h, mw2l, mb2, 0, nullptr, nullptr, mw3, mb3, out + (size_t)MM * 3, 0);
    }
}

// round 16
// speedup vs baseline: 1.3375x; 1.3375x over previous
#include <cuda_runtime.h>
#include <cuda_bf16.h>
#include <math.h>
#include <stdint.h>

#define BB 4
#define TT 16384
#define SSZ 8192
#define DD 256
#define GG 512
#define KX 259
#define MM (BB*TT)              /* 65536 rows */
#define NTILE (MM/128)          /* 512 row tiles */
#define KNN 8

#if defined(__CUDA_ARCH_FEAT_SM103_ALL) || defined(__CUDA_ARCH_FEAT_SM100_ALL) || \
    defined(__CUDA_ARCH_FEAT_SM101_ALL) || defined(__CUDA_ARCH_SPECIFIC__)
#define TC_ENABLED 1
#else
#define TC_ENABLED 0
#endif

// ---------------------------------------------------------------------------
// Static device scratch (x: cols 0..255 local, 256..258 tmpl, 259..319 pad=0)
// ---------------------------------------------------------------------------
__device__ __align__(16) __nv_bfloat16 g_xh [(size_t)NTILE * 5 * 8192];
__device__ __align__(16) __nv_bfloat16 g_xl [(size_t)NTILE * 5 * 8192];
__device__ __align__(16) __nv_bfloat16 g_h1h[(size_t)NTILE * 4 * 8192];
__device__ __align__(16) __nv_bfloat16 g_h1l[(size_t)NTILE * 4 * 8192];
__device__ __align__(16) __nv_bfloat16 g_m1h[(size_t)NTILE * 2 * 8192];
__device__ __align__(16) __nv_bfloat16 g_m1l[(size_t)NTILE * 2 * 8192];

__device__ __align__(16) __nv_bfloat16 g_dw1h[5 * 256 * 64], g_dw1l[5 * 256 * 64];
__device__ __align__(16) __nv_bfloat16 g_dw2h[4 * 256 * 64], g_dw2l[4 * 256 * 64];
__device__ __align__(16) __nv_bfloat16 g_mw1h[5 * 128 * 64], g_mw1l[5 * 128 * 64];
__device__ __align__(16) __nv_bfloat16 g_mw2h[2 * 64 * 64],  g_mw2l[2 * 64 * 64];

__device__ float g_gbd[4 * 256];
__device__ float g_gbm[4 * 128];

// ---------------------------------------------------------------------------
// PTX helpers
// ---------------------------------------------------------------------------
__device__ __forceinline__ uint32_t smem_u32(const void* p) {
    uint32_t a;
    asm("{ .reg .u64 t; cvta.to.shared.u64 t, %1; cvt.u32.u64 %0, t; }" : "=r"(a) : "l"(p));
    return a;
}
__device__ __forceinline__ uint32_t elect_one_pred() {
    uint32_t p;
    asm volatile("{ .reg .pred p; elect.sync _|p, 0xFFFFFFFF; selp.b32 %0, 1, 0, p; }" : "=r"(p));
    return p;
}
#define SWZ128(x) ((x) ^ (((x) >> 3) & 0x70))

static __device__ constexpr uint64_t SMEM_DESC_BASE_SW128 =
    (uint64_t(2) << 61) | (uint64_t(1) << 46) | (uint64_t(64) << 32) | (uint64_t(1) << 16);
#define MAKE_DESC(addr) (SMEM_DESC_BASE_SW128 | ((uint64_t)((addr) >> 4) & 0x3FFF))

#if TC_ENABLED
#define TC_ALLOC(sm, n)  asm volatile("tcgen05.alloc.cta_group::1.sync.aligned.shared::cta.b32 [%0], %1;" :: "r"((uint32_t)(sm)), "r"((uint32_t)(n)) : "memory")
#define TC_DEALLOC(t, n) asm volatile("tcgen05.dealloc.cta_group::1.sync.aligned.b32 %0, %1;" :: "r"(t), "r"((uint32_t)(n)))
#define TC_RELINQ()      asm volatile("tcgen05.relinquish_alloc_permit.cta_group::1.sync.aligned;")
#define TC_COMMIT(mb)    asm volatile("tcgen05.commit.cta_group::1.mbarrier::arrive::one.shared::cluster.b64 [%0];" :: "r"((uint32_t)(mb)) : "memory")
#define TC_FENCE_AFTER() asm volatile("tcgen05.fence::after_thread_sync;" ::: "memory")
#define TC_WAIT_LD()     asm volatile("tcgen05.wait::ld.sync.aligned;" ::: "memory")
#else
#define TC_ALLOC(sm, n)
#define TC_DEALLOC(t, n)
#define TC_RELINQ()
#define TC_COMMIT(mb)
#define TC_FENCE_AFTER()
#define TC_WAIT_LD()
#endif

#define MBAR_INIT(mb, c) asm volatile("mbarrier.init.shared.b64 [%0], %1;" :: "r"((uint32_t)(mb)), "r"((uint32_t)(c)) : "memory")
#define MBAR_EXPECT_TX(mb, n) asm volatile("mbarrier.arrive.expect_tx.shared.b64 _, [%0], %1;" :: "r"((uint32_t)(mb)), "r"((uint32_t)(n)) : "memory")
#define BULK_G2S(dst, src, bytes, mb) \
    asm volatile("cp.async.bulk.shared::cluster.global.mbarrier::complete_tx::bytes [%0], [%1], %2, [%3];" \
        :: "r"((uint32_t)(dst)), "l"(src), "r"((uint32_t)(bytes)), "r"((uint32_t)(mb)) : "memory")
#define BULK_S2G(gdst, ssrc, bytes) \
    asm volatile("cp.async.bulk.global.shared::cta.bulk_group [%0], [%1], %2;" \
        :: "l"(gdst), "r"((uint32_t)(ssrc)), "r"((uint32_t)(bytes)) : "memory")
#define FENCE_ASYNC() asm volatile("fence.proxy.async.shared::cta;" ::: "memory")

__device__ __forceinline__ void mbar_wait(uint32_t mb, uint32_t parity) {
    uint32_t done;
    asm volatile(
        "{ .reg .pred p; mbarrier.try_wait.parity.acquire.cta.shared::cta.b64 p, [%1], %2; selp.b32 %0, 1, 0, p; }"
        : "=r"(done) : "r"(mb), "r"(parity) : "memory");
    if (!done) {
        asm volatile(
            "{ .reg .pred P1;\n"
            "W%=: mbarrier.try_wait.parity.acquire.cta.shared::cta.b64 P1, [%0], %1, 0x989680;\n"
            "@P1 bra.uni D%=;\n bra.uni W%=;\n D%=: }"
            :: "r"(mb), "r"(parity) : "memory");
    }
}

__device__ __forceinline__ void mma_f16_ss(uint32_t d, uint64_t a, uint64_t b,
                                           uint32_t idesc, uint32_t en) {
#if TC_ENABLED
    asm volatile(
        "{ .reg .pred p; setp.ne.u32 p, %4, 0;\n"
        "tcgen05.mma.cta_group::1.kind::f16 [%0], %1, %2, %3, {%5,%5,%5,%5}, p; }"
        :: "r"(d), "l"(a), "l"(b), "r"(idesc), "r"(en), "r"(0u) : "memory");
#endif
}

__device__ __forceinline__ void tc_ld_x32(uint32_t* r, uint32_t addr) {
#if TC_ENABLED
    asm volatile("tcgen05.ld.sync.aligned.32x32b.x32.b32 "
        "{%0,%1,%2,%3,%4,%5,%6,%7,%8,%9,%10,%11,%12,%13,%14,%15,"
        "%16,%17,%18,%19,%20,%21,%22,%23,%24,%25,%26,%27,%28,%29,%30,%31}, [%32];"
        : "=r"(r[0]),"=r"(r[1]),"=r"(r[2]),"=r"(r[3]),"=r"(r[4]),"=r"(r[5]),"=r"(r[6]),"=r"(r[7]),
          "=r"(r[8]),"=r"(r[9]),"=r"(r[10]),"=r"(r[11]),"=r"(r[12]),"=r"(r[13]),"=r"(r[14]),"=r"(r[15]),
          "=r"(r[16]),"=r"(r[17]),"=r"(r[18]),"=r"(r[19]),"=r"(r[20]),"=r"(r[21]),"=r"(r[22]),"=r"(r[23]),
          "=r"(r[24]),"=r"(r[25]),"=r"(r[26]),"=r"(r[27]),"=r"(r[28]),"=r"(r[29]),"=r"(r[30]),"=r"(r[31])
        : "r"(addr));
#endif
}

// ---------------------------------------------------------------------------
// Kernel 1: KNN (k=8), 2 threads/point, min-of-8 batched scan (exactness-
// preserving), smem merge, gather/mean + direct packed x emission.
// ---------------------------------------------------------------------------
#define PPB 256
#define NTH 512
#define SCH 2048

__device__ __forceinline__ void heap_insert(
    float d2, int idx, float bd[KNN], int bi[KNN], float& wmax, int& wslot)
{
#pragma unroll
    for (int i = 0; i < KNN; i++)
        if (i == wslot) { bd[i] = d2; bi[i] = idx; }
    float wm = -3.4e38f; int ws = 0;
#pragma unroll
    for (int i = 0; i < KNN; i++)
        if (bd[i] > wm) { wm = bd[i]; ws = i; }
    wmax = wm; wslot = ws;
}

__global__ void __launch_bounds__(NTH) knn_build_xpk(
    const float* __restrict__ tmpl, const float* __restrict__ surf,
    const float* __restrict__ pfeat)
{
    __shared__ float4 ssurf[SCH];
    __shared__ int    sidx[PPB * KNN];
    __shared__ float  sdB[PPB * KNN];
    __shared__ int    siB[PPB * KNN];

    const int b  = blockIdx.x / (TT / PPB);
    const int p0 = (blockIdx.x % (TT / PPB)) * PPB;
    const int tid = threadIdx.x;
    const int pl  = tid & (PPB - 1);
    const int half = tid >> 8;

    const int pt = p0 + pl;
    const size_t trow = ((size_t)b * TT + pt) * 3;
    const float tx = tmpl[trow + 0], ty = tmpl[trow + 1], tz = tmpl[trow + 2];
    const float tsq = tx * tx + ty * ty + tz * tz;
    const float ntx = -2.f * tx, nty = -2.f * ty, ntz = -2.f * tz;

    float bd[KNN]; int bi[KNN];
#pragma unroll
    for (int i = 0; i < KNN; i++) { bd[i] = 3.4e38f; bi[i] = 0; }
    float wmax = 3.4e38f; int wslot = 0;

    for (int c0 = 0; c0 < SSZ; c0 += SCH) {
        __syncthreads();
        for (int i = tid; i < SCH; i += NTH) {
            size_t srow = ((size_t)b * SSZ + c0 + i) * 3;
            float sx = surf[srow], sy = surf[srow + 1], sz = surf[srow + 2];
            ssurf[i] = make_float4(sx, sy, sz, sx * sx + sy * sy + sz * sz);
        }
        __syncthreads();
        const int sbeg = half * (SCH / 2);
        // min-of-8 batched scan: identical update sequence to sequential scan
        for (int s = sbeg; s < sbeg + SCH / 2; s += 8) {
            float e[8];
#pragma unroll
            for (int j = 0; j < 8; j++) {
                float4 v = ssurf[s + j];
                e[j] = fmaf(ntx, v.x, fmaf(nty, v.y, fmaf(ntz, v.z, tsq + v.w)));
            }
            float m01 = fminf(e[0], e[1]), m23 = fminf(e[2], e[3]);
            float m45 = fminf(e[4], e[5]), m67 = fminf(e[6], e[7]);
            float m = fminf(fminf(m01, m23), fminf(m45, m67));
            if (m < wmax) {
#pragma unroll
                for (int j = 0; j < 8; j++)
                    if (e[j] < wmax) heap_insert(e[j], c0 + s + j, bd, bi, wmax, wslot);
            }
        }
    }

    // merge: half B publishes, half A folds B's 8 candidates into its heap
    if (half == 1) {
#pragma unroll
        for (int i = 0; i < KNN; i++) {
            sdB[pl * KNN + i] = bd[i];
            siB[pl * KNN + i] = bi[i];
        }
    }
    __syncthreads();
    if (half == 0) {
#pragma unroll
        for (int n = 0; n < KNN; n++) {
            float d2 = sdB[pl * KNN + n];
            int   ii = siB[pl * KNN + n];
            if (d2 < wmax) heap_insert(d2, ii, bd, bi, wmax, wslot);
        }
#pragma unroll
        for (int i = 0; i < KNN; i++) sidx[pl * KNN + i] = bi[i];
    }
    __syncthreads();

    // gather + packed emission: 16 warps x 16 points
    const int lane = tid & 31, wid = tid >> 5;
    for (int q = 0; q < PPB / 16; q++) {
        const int lp = wid * (PPB / 16) + q;
        float acc[8];
#pragma unroll
        for (int j = 0; j < 8; j++) acc[j] = 0.f;
#pragma unroll
        for (int n = 0; n < KNN; n++) {
            const int sI = sidx[lp * KNN + n];
            const float4* rowp = (const float4*)(pfeat + ((size_t)b * SSZ + sI) * DD + lane * 8);
            float4 a0 = rowp[0], a1 = rowp[1];
            acc[0] += a0.x; acc[1] += a0.y; acc[2] += a0.z; acc[3] += a0.w;
            acc[4] += a1.x; acc[5] += a1.y; acc[6] += a1.z; acc[7] += a1.w;
        }
        const int row = b * TT + p0 + lp;
        const int tile = row >> 7, rloc = row & 127;
        __align__(16) __nv_bfloat16 h[8], l[8];
#pragma unroll
        for (int j = 0; j < 8; j++) {
            float v = acc[j] * 0.125f;
            h[j] = __float2bfloat16(v);
            l[j] = __float2bfloat16(v - __bfloat162float(h[j]));
        }
        const uint32_t off = SWZ128((uint32_t)(rloc * 128 + ((lane & 7) << 4)));
        const size_t blk = ((size_t)(tile * 5) + (lane >> 3)) * 16384 + off;
        *(uint4*)((char*)g_xh + blk) = *(const uint4*)h;
        *(uint4*)((char*)g_xl + blk) = *(const uint4*)l;
        if (lane < 3) {
            float v = tmpl[(size_t)row * 3 + lane];
            __nv_bfloat16 hh = __float2bfloat16(v);
            __nv_bfloat16 ll = __float2bfloat16(v - __bfloat162float(hh));
            const uint32_t o2 = SWZ128((uint32_t)(rloc * 128)) + (lane << 1);
            const size_t b2 = ((size_t)(tile * 5) + 4) * 16384 + o2;
            *(__nv_bfloat16*)((char*)g_xh + b2) = hh;
            *(__nv_bfloat16*)((char*)g_xl + b2) = ll;
        }
    }
}

// ---------------------------------------------------------------------------
// prep jobs (layer-1 weights use permuted row map: k'<256 -> k'+3; 256..258 -> k'-256)
// ---------------------------------------------------------------------------
__device__ __forceinline__ void pack_w1_elem(
    const float* W, __nv_bfloat16* hi, __nv_bfloat16* lo, int idx, int N)
{
    int n = idx / 320, kp = idx - n * 320;
    float v;
    if (kp < 256)       v = W[(size_t)(kp + 3) * N + n];
    else if (kp < 259)  v = W[(size_t)(kp - 256) * N + n];
    else                v = 0.f;
    __nv_bfloat16 h = __float2bfloat16(v);
    int ch = kp >> 6, kc = kp & 63;
    uint32_t e = (uint32_t)ch * (N * 64) + (SWZ128((uint32_t)(n * 128 + kc * 2)) >> 1);
    hi[e] = h;
    lo[e] = __float2bfloat16(v - __bfloat162float(h));
}

__device__ __forceinline__ void pack_w_elem(
    const float* W, __nv_bfloat16* hi, __nv_bfloat16* lo,
    int idx, int N, int Kpad)
{
    int n = idx / Kpad, k = idx - n * Kpad;
    float v = W[(size_t)k * N + n];
    __nv_bfloat16 h = __float2bfloat16(v);
    int ch = k >> 6, kc = k & 63;
    uint32_t e = (uint32_t)ch * (N * 64) + (SWZ128((uint32_t)(n * 128 + kc * 2)) >> 1);
    hi[e] = h;
    lo[e] = __float2bfloat16(v - __bfloat162float(h));
}

__global__ void __launch_bounds__(256) prep_job(
    int job,
    const float* __restrict__ W, const float* __restrict__ bias_in,
    const float* __restrict__ gfeat)
{
    const int bid = blockIdx.x, tid = threadIdx.x;
    if (job == 0) {
        pack_w1_elem(W, g_dw1h, g_dw1l, bid * 256 + tid, 256);
    } else if (job == 1) {
        pack_w_elem(W, g_dw2h, g_dw2l, bid * 256 + tid, 256, 256);
    } else if (job == 2) {
        pack_w1_elem(W, g_mw1h, g_mw1l, bid * 256 + tid, 128);
    } else if (job == 3) {
        pack_w_elem(W, g_mw2h, g_mw2l, bid * 256 + tid, 64, 128);
    } else {
        int b = bid;
        float s = bias_in[tid];
#pragma unroll 4
        for (int k = 0; k < GG; k++)
            s = fmaf(gfeat[b * GG + k], W[(size_t)(KX + k) * 256 + tid], s);
        g_gbd[b * 256 + tid] = s;
    }
}

__global__ void __launch_bounds__(256) prep_gbm(
    const float* __restrict__ mw1, const float* __restrict__ mb1,
    const float* __restrict__ gfeat)
{
    const int b = blockIdx.x, tid = threadIdx.x;
    if (tid < 128) {
        float s = mb1[tid];
#pragma unroll 4
        for (int k = 0; k < GG; k++)
            s = fmaf(gfeat[b * GG + k], mw1[(size_t)(KX + k) * 128 + tid], s);
        g_gbm[b * 128 + tid] = s;
    }
}

// ---------------------------------------------------------------------------
// tcgen05 GEMM with fused epilogue (round-14 proven version).
// ---------------------------------------------------------------------------
#define OUT_PACK 0
#define OUT_DISP 1
#define OUT_MAT  2

template<int NT, int OMODE>
__global__ void __launch_bounds__(128) gemm_tc3(
    const __nv_bfloat16* __restrict__ Ah, const __nv_bfloat16* __restrict__ Al, int nch,
    const __nv_bfloat16* __restrict__ Bh, const __nv_bfloat16* __restrict__ Bl,
    const float* __restrict__ bias, int bstride,
    __nv_bfloat16* __restrict__ Oh, __nv_bfloat16* __restrict__ Ol,
    const float* __restrict__ w3, const float* __restrict__ b3,
    float* __restrict__ out)
{
#if TC_ENABLED
    extern __shared__ __align__(1024) char smem[];
    constexpr uint32_t B_OFF = 32768u;
    constexpr uint32_t STAGE = 32768u + NT * 256u;
    constexpr int SWN = (OMODE == OUT_DISP) ? 768 : ((OMODE == OUT_MAT) ? 64 : 1);
    __shared__ uint32_t s_tmem;
    __shared__ __align__(8) uint64_t s_mb[4];
    __shared__ float sb[NT];
    __shared__ float sw[SWN];

    const uint32_t smb  = smem_u32(smem);
    const uint32_t mbb  = smem_u32(&s_mb[0]);
    const int tid = threadIdx.x, wid = tid >> 5, lane = tid & 31;
    const int tile = blockIdx.x, bm = tile * 128;

    for (int i = tid; i < NT; i += 128) sb[i] = bias[(bm >> 14) * bstride + i];
    if (OMODE != OUT_PACK)
        for (int i = tid; i < SWN; i += 128) sw[i] = w3[i];
    if (wid == 0) { TC_ALLOC(smem_u32(&s_tmem), NT); TC_RELINQ(); }
    if (tid == 0)
        for (int i = 0; i < 4; i++) MBAR_INIT(mbb + i * 8, 1);
    __syncthreads();
    uint32_t tmem;
    asm volatile("ld.shared.b32 %0, [%1];" : "=r"(tmem) : "r"(smem_u32(&s_tmem)));

    const uint32_t idesc = (1u << 4) | (1u << 7) | (1u << 10) | ((NT / 8) << 17) | (8u << 24);

    if (wid == 0) {
        uint32_t pd[2] = {0u, 0u}, pm[2] = {0u, 0u};
        const uint32_t ep = elect_one_pred();

        if (ep) {
            for (int c = 0; c < 2 && c < nch; c++) {
                const int s = c & 1;
                const uint32_t st = smb + s * STAGE;
                MBAR_EXPECT_TX(mbb + s * 8, STAGE);
                BULK_G2S(st,                    Ah + ((size_t)tile * nch + c) * 8192, 16384, mbb + s * 8);
                BULK_G2S(st + 16384,            Al + ((size_t)tile * nch + c) * 8192, 16384, mbb + s * 8);
                BULK_G2S(st + B_OFF,            Bh + (size_t)c * NT * 64, NT * 128, mbb + s * 8);
                BULK_G2S(st + B_OFF + NT * 128, Bl + (size_t)c * NT * 64, NT * 128, mbb + s * 8);
            }
        }
        for (int ch = 0; ch < nch; ch++) {
            const int s = ch & 1;
            const uint32_t st = smb + s * STAGE;
            mbar_wait(mbb + s * 8, pd[s]); pd[s] ^= 1;
            if (ep) {
                uint64_t ah = MAKE_DESC(st), al = MAKE_DESC(st + 16384);
                uint64_t bh = MAKE_DESC(st + B_OFF), bl = MAKE_DESC(st + B_OFF + NT * 128);
#pragma unroll
                for (int ks = 0; ks < 4; ks++) {
                    uint32_t en0 = (ch == 0 && ks == 0) ? 0u : 1u;
                    mma_f16_ss(tmem, ah + ks * 2, bh + ks * 2, idesc, en0);
                    mma_f16_ss(tmem, ah + ks * 2, bl + ks * 2, idesc, 1u);
                    mma_f16_ss(tmem, al + ks * 2, bh + ks * 2, idesc, 1u);
                }
                TC_COMMIT(mbb + 16 + s * 8);
            }
            if (ch + 2 < nch) {
                mbar_wait(mbb + 16 + s * 8, pm[s]); pm[s] ^= 1;
                if (ep) {
                    const int c = ch + 2;
                    MBAR_EXPECT_TX(mbb + s * 8, STAGE);
                    BULK_G2S(st,                    Ah + ((size_t)tile * nch + c) * 8192, 16384, mbb + s * 8);
                    BULK_G2S(st + 16384,            Al + ((size_t)tile * nch + c) * 8192, 16384, mbb + s * 8);
                    BULK_G2S(st + B_OFF,            Bh + (size_t)c * NT * 64, NT * 128, mbb + s * 8);
                    BULK_G2S(st + B_OFF + NT * 128, Bl + (size_t)c * NT * 64, NT * 128, mbb + s * 8);
                }
            }
        }
        const int fs = (nch - 1) & 1;
        mbar_wait(mbb + 16 + fs * 8, pm[fs]);
    }
    __syncthreads();
    TC_FENCE_AFTER();

    const int rloc = wid * 32 + lane;
    const size_t row = (size_t)bm + rloc;

    if (OMODE == OUT_PACK) {
        constexpr int NCH2 = NT / 64;
#pragma unroll
        for (int c0 = 0; c0 < NT; c0 += 32) {
            uint32_t r[32];
            tc_ld_x32(r, tmem + c0);
            TC_WAIT_LD();
#pragma unroll
            for (int j4 = 0; j4 < 8; j4++) {
                const int c = c0 + j4 * 4;
                float v0 = fmaxf(__uint_as_float(r[j4 * 4 + 0]) + sb[c + 0], 0.f);
                float v1 = fmaxf(__uint_as_float(r[j4 * 4 + 1]) + sb[c + 1], 0.f);
                float v2 = fmaxf(__uint_as_float(r[j4 * 4 + 2]) + sb[c + 2], 0.f);
                float v3 = fmaxf(__uint_as_float(r[j4 * 4 + 3]) + sb[c + 3], 0.f);
                __align__(8) __nv_bfloat16 hh[4], ll[4];
                hh[0] = __float2bfloat16(v0); ll[0] = __float2bfloat16(v0 - __bfloat162float(hh[0]));
                hh[1] = __float2bfloat16(v1); ll[1] = __float2bfloat16(v1 - __bfloat162float(hh[1]));
                hh[2] = __float2bfloat16(v2); ll[2] = __float2bfloat16(v2 - __bfloat162float(hh[2]));
                hh[3] = __float2bfloat16(v3); ll[3] = __float2bfloat16(v3 - __bfloat162float(hh[3]));
                const int chunk = c >> 6, cc = c & 63;
                uint32_t off = (uint32_t)chunk * 16384u
                             + SWZ128((uint32_t)(rloc * 128 + ((cc >> 3) << 4)))
                             + (uint32_t)((cc & 7) << 1);
                *(uint64_t*)(smem + off)                   = *(const uint64_t*)hh;
                *(uint64_t*)(smem + NCH2 * 16384u + off)   = *(const uint64_t*)ll;
            }
        }
        __syncthreads();
        if (tid == 0) {
            FENCE_ASYNC();
            for (int ch = 0; ch < NCH2; ch++) {
                BULK_S2G(Oh + ((size_t)tile * NCH2 + ch) * 8192, smb + ch * 16384u, 16384);
                BULK_S2G(Ol + ((size_t)tile * NCH2 + ch) * 8192, smb + (NCH2 + ch) * 16384u, 16384);
            }
            asm volatile("cp.async.bulk.commit_group;" ::: "memory");
            asm volatile("cp.async.bulk.wait_group 0;" ::: "memory");
        }
    } else {
        float a0 = 0.f, a1 = 0.f, a2 = 0.f;
#pragma unroll
        for (int c0 = 0; c0 < NT; c0 += 32) {
            uint32_t r[32];
            tc_ld_x32(r, tmem + c0);
            TC_WAIT_LD();
#pragma unroll
            for (int j4 = 0; j4 < 8; j4++) {
                const int c = c0 + j4 * 4;
#pragma unroll
                for (int k = 0; k < 4; k++) {
                    float v = fmaxf(__uint_as_float(r[j4 * 4 + k]) + sb[c + k], 0.f);
                    if (OMODE == OUT_DISP) {
                        a0 = fmaf(v, sw[(c + k) * 3 + 0], a0);
                        a1 = fmaf(v, sw[(c + k) * 3 + 1], a1);
                        a2 = fmaf(v, sw[(c + k) * 3 + 2], a2);
                    } else {
                        a0 = fmaf(v, sw[c + k], a0);
                    }
                }
            }
        }
        if (OMODE == OUT_DISP) {
            out[row * 3 + 0] = a0 + b3[0];
            out[row * 3 + 1] = a1 + b3[1];
            out[row * 3 + 2] = a2 + b3[2];
        } else {
            float z = a0 + b3[0];
            out[row] = 1.f / (1.f + expf(-z));
        }
    }
    __syncthreads();
    if (wid == 0) TC_DEALLOC(tmem, NT);
#endif  // TC_ENABLED
}

// ---------------------------------------------------------------------------
extern "C" void kernel_launch(void* const* d_in, const int* in_sizes, int n_in,
                              void* d_out, int out_size)
{
    const float* tmpl  = (const float*)d_in[0];
    const float* surf  = (const float*)d_in[1];
    const float* gfeat = (const float*)d_in[2];
    const float* pfeat = (const float*)d_in[3];
    const float* dw1 = (const float*)d_in[4];
    const float* db1 = (const float*)d_in[5];
    const float* dw2 = (const float*)d_in[6];
    const float* db2 = (const float*)d_in[7];
    const float* dw3 = (const float*)d_in[8];
    const float* db3 = (const float*)d_in[9];
    const float* mw1 = (const float*)d_in[10];
    const float* mb1 = (const float*)d_in[11];
    const float* mw2 = (const float*)d_in[12];
    const float* mb2 = (const float*)d_in[13];
    const float* mw3 = (const float*)d_in[14];
    const float* mb3 = (const float*)d_in[15];
    float* out = (float*)d_out;

    float *gbd, *gbm;
    cudaGetSymbolAddress((void**)&gbd, g_gbd);
    cudaGetSymbolAddress((void**)&gbm, g_gbm);
    __nv_bfloat16 *xh, *xl, *h1h, *h1l, *m1h, *m1l;
    __nv_bfloat16 *dw1h, *dw1l, *dw2h, *dw2l, *mw1h, *mw1l, *mw2h, *mw2l;
    cudaGetSymbolAddress((void**)&xh,  g_xh);
    cudaGetSymbolAddress((void**)&xl,  g_xl);
    cudaGetSymbolAddress((void**)&h1h, g_h1h);
    cudaGetSymbolAddress((void**)&h1l, g_h1l);
    cudaGetSymbolAddress((void**)&m1h, g_m1h);
    cudaGetSymbolAddress((void**)&m1l, g_m1l);
    cudaGetSymbolAddress((void**)&dw1h, g_dw1h);
    cudaGetSymbolAddress((void**)&dw1l, g_dw1l);
    cudaGetSymbolAddress((void**)&dw2h, g_dw2h);
    cudaGetSymbolAddress((void**)&dw2l, g_dw2l);
    cudaGetSymbolAddress((void**)&mw1h, g_mw1h);
    cudaGetSymbolAddress((void**)&mw1l, g_mw1l);
    cudaGetSymbolAddress((void**)&mw2h, g_mw2h);
    cudaGetSymbolAddress((void**)&mw2l, g_mw2l);

    const int SM1 = 2 * (32768 + 256 * 256);
    const int SM3 = 2 * (32768 + 128 * 256);
    const int SM4 = 2 * (32768 +  64 * 256);
    cudaFuncSetAttribute((const void*)gemm_tc3<256, OUT_PACK>, cudaFuncAttributeMaxDynamicSharedMemorySize, SM1);
    cudaFuncSetAttribute((const void*)gemm_tc3<256, OUT_DISP>, cudaFuncAttributeMaxDynamicSharedMemorySize, SM1);
    cudaFuncSetAttribute((const void*)gemm_tc3<128, OUT_PACK>, cudaFuncAttributeMaxDynamicSharedMemorySize, SM3);
    cudaFuncSetAttribute((const void*)gemm_tc3<64,  OUT_MAT>,  cudaFuncAttributeMaxDynamicSharedMemorySize, SM4);

    static cudaStream_t s1 = nullptr;
    static cudaEvent_t ev0 = nullptr, evP = nullptr, evX = nullptr, evM = nullptr;
    static int forked = -1;
    if (forked < 0) {
        bool ok = cudaStreamCreateWithFlags(&s1, cudaStreamNonBlocking) == cudaSuccess
               && cudaEventCreateWithFlags(&ev0, cudaEventDisableTiming) == cudaSuccess
               && cudaEventCreateWithFlags(&evP, cudaEventDisableTiming) == cudaSuccess
               && cudaEventCreateWithFlags(&evX, cudaEventDisableTiming) == cudaSuccess
               && cudaEventCreateWithFlags(&evM, cudaEventDisableTiming) == cudaSuccess;
        forked = ok ? 1 : 0;
    }

    if (forked == 1) {
        cudaEventRecord(ev0, 0);
        cudaStreamWaitEvent(s1, ev0, 0);
        prep_job<<<320, 256, 0, s1>>>(0, dw1, nullptr, gfeat);
        prep_job<<<256, 256, 0, s1>>>(1, dw2, nullptr, gfeat);
        prep_job<<<160, 256, 0, s1>>>(2, mw1, nullptr, gfeat);
        prep_job<<<32,  256, 0, s1>>>(3, mw2, nullptr, gfeat);
        prep_job<<<4,   256, 0, s1>>>(4, dw1, db1, gfeat);
        prep_gbm<<<4,   256, 0, s1>>>(mw1, mb1, gfeat);
        cudaEventRecord(evP, s1);

        knn_build_xpk<<<MM / PPB, NTH>>>(tmpl, surf, pfeat);
        cudaEventRecord(evX, 0);

        cudaStreamWaitEvent(s1, evX, 0);
        gemm_tc3<128, OUT_PACK><<<NTILE, 128, SM3, s1>>>(
            xh, xl, 5, mw1h, mw1l, gbm, 128, m1h, m1l, nullptr, nullptr, nullptr);
        gemm_tc3<64, OUT_MAT><<<NTILE, 128, SM4, s1>>>(
            m1h, m1l, 2, mw2h, mw2l, mb2, 0, nullptr, nullptr, mw3, mb3, out + (size_t)MM * 3);
        cudaEventRecord(evM, s1);

        cudaStreamWaitEvent(0, evP, 0);
        gemm_tc3<256, OUT_PACK><<<NTILE, 128, SM1>>>(
            xh, xl, 5, dw1h, dw1l, gbd, 256, h1h, h1l, nullptr, nullptr, nullptr);
        gemm_tc3<256, OUT_DISP><<<NTILE, 128, SM1>>>(
            h1h, h1l, 4, dw2h, dw2l, db2, 0, nullptr, nullptr, dw3, db3, out);
        cudaStreamWaitEvent(0, evM, 0);
    } else {
        prep_job<<<320, 256>>>(0, dw1, nullptr, gfeat);
        prep_job<<<256, 256>>>(1, dw2, nullptr, gfeat);
        prep_job<<<160, 256>>>(2, mw1, nullptr, gfeat);
        prep_job<<<32,  256>>>(3, mw2, nullptr, gfeat);
        prep_job<<<4,   256>>>(4, dw1, db1, gfeat);
        prep_gbm<<<4,   256>>>(mw1, mb1, gfeat);
        knn_build_xpk<<<MM / PPB, NTH>>>(tmpl, surf, pfeat);
        gemm_tc3<256, OUT_PACK><<<NTILE, 128, SM1>>>(
            xh, xl, 5, dw1h, dw1l, gbd, 256, h1h, h1l, nullptr, nullptr, nullptr);
        gemm_tc3<128, OUT_PACK><<<NTILE, 128, SM3>>>(
            xh, xl, 5, mw1h, mw1l, gbm, 128, m1h, m1l, nullptr, nullptr, nullptr);
        gemm_tc3<256, OUT_DISP><<<NTILE, 128, SM1>>>(
            h1h, h1l, 4, dw2h, dw2l, db2, 0, nullptr, nullptr, dw3, db3, out);
        gemm_tc3<64, OUT_MAT><<<NTILE, 128, SM4>>>(
            m1h, m1l, 2, mw2h, mw2l, mb2, 0, nullptr, nullptr, mw3, mb3, out + (size_t)MM * 3);
    }
}

// round 17
// speedup vs baseline: 1.4299x; 1.0691x over previous
#include <cuda_runtime.h>
#include <cuda_bf16.h>
#include <math.h>
#include <stdint.h>

#define BB 4
#define TT 16384
#define SSZ 8192
#define DD 256
#define GG 512
#define KX 259
#define MM (BB*TT)              /* 65536 rows */
#define NTILE (MM/128)          /* 512 row tiles */
#define KNN 8

#if defined(__CUDA_ARCH_FEAT_SM103_ALL) || defined(__CUDA_ARCH_FEAT_SM100_ALL) || \
    defined(__CUDA_ARCH_FEAT_SM101_ALL) || defined(__CUDA_ARCH_SPECIFIC__)
#define TC_ENABLED 1
#else
#define TC_ENABLED 0
#endif

// ---------------------------------------------------------------------------
// Static device scratch (x: cols 0..255 local, 256..258 tmpl, 259..319 pad=0)
// ---------------------------------------------------------------------------
__device__ __align__(16) __nv_bfloat16 g_xh [(size_t)NTILE * 5 * 8192];
__device__ __align__(16) __nv_bfloat16 g_xl [(size_t)NTILE * 5 * 8192];
__device__ __align__(16) __nv_bfloat16 g_h1h[(size_t)NTILE * 4 * 8192];
__device__ __align__(16) __nv_bfloat16 g_h1l[(size_t)NTILE * 4 * 8192];
__device__ __align__(16) __nv_bfloat16 g_m1h[(size_t)NTILE * 2 * 8192];
__device__ __align__(16) __nv_bfloat16 g_m1l[(size_t)NTILE * 2 * 8192];

__device__ __align__(16) __nv_bfloat16 g_dw1h[5 * 256 * 64], g_dw1l[5 * 256 * 64];
__device__ __align__(16) __nv_bfloat16 g_dw2h[4 * 256 * 64], g_dw2l[4 * 256 * 64];
__device__ __align__(16) __nv_bfloat16 g_mw1h[5 * 128 * 64], g_mw1l[5 * 128 * 64];
__device__ __align__(16) __nv_bfloat16 g_mw2h[2 * 64 * 64],  g_mw2l[2 * 64 * 64];

__device__ float g_gbd[4 * 256];
__device__ float g_gbm[4 * 128];

// ---------------------------------------------------------------------------
// PTX helpers
// ---------------------------------------------------------------------------
__device__ __forceinline__ uint32_t smem_u32(const void* p) {
    uint32_t a;
    asm("{ .reg .u64 t; cvta.to.shared.u64 t, %1; cvt.u32.u64 %0, t; }" : "=r"(a) : "l"(p));
    return a;
}
__device__ __forceinline__ uint32_t elect_one_pred() {
    uint32_t p;
    asm volatile("{ .reg .pred p; elect.sync _|p, 0xFFFFFFFF; selp.b32 %0, 1, 0, p; }" : "=r"(p));
    return p;
}
#define SWZ128(x) ((x) ^ (((x) >> 3) & 0x70))

static __device__ constexpr uint64_t SMEM_DESC_BASE_SW128 =
    (uint64_t(2) << 61) | (uint64_t(1) << 46) | (uint64_t(64) << 32) | (uint64_t(1) << 16);
#define MAKE_DESC(addr) (SMEM_DESC_BASE_SW128 | ((uint64_t)((addr) >> 4) & 0x3FFF))

#if TC_ENABLED
#define TC_ALLOC(sm, n)  asm volatile("tcgen05.alloc.cta_group::1.sync.aligned.shared::cta.b32 [%0], %1;" :: "r"((uint32_t)(sm)), "r"((uint32_t)(n)) : "memory")
#define TC_DEALLOC(t, n) asm volatile("tcgen05.dealloc.cta_group::1.sync.aligned.b32 %0, %1;" :: "r"(t), "r"((uint32_t)(n)))
#define TC_RELINQ()      asm volatile("tcgen05.relinquish_alloc_permit.cta_group::1.sync.aligned;")
#define TC_COMMIT(mb)    asm volatile("tcgen05.commit.cta_group::1.mbarrier::arrive::one.shared::cluster.b64 [%0];" :: "r"((uint32_t)(mb)) : "memory")
#define TC_FENCE_AFTER() asm volatile("tcgen05.fence::after_thread_sync;" ::: "memory")
#define TC_WAIT_LD()     asm volatile("tcgen05.wait::ld.sync.aligned;" ::: "memory")
#else
#define TC_ALLOC(sm, n)
#define TC_DEALLOC(t, n)
#define TC_RELINQ()
#define TC_COMMIT(mb)
#define TC_FENCE_AFTER()
#define TC_WAIT_LD()
#endif

#define MBAR_INIT(mb, c) asm volatile("mbarrier.init.shared.b64 [%0], %1;" :: "r"((uint32_t)(mb)), "r"((uint32_t)(c)) : "memory")
#define MBAR_EXPECT_TX(mb, n) asm volatile("mbarrier.arrive.expect_tx.shared.b64 _, [%0], %1;" :: "r"((uint32_t)(mb)), "r"((uint32_t)(n)) : "memory")
#define BULK_G2S(dst, src, bytes, mb) \
    asm volatile("cp.async.bulk.shared::cluster.global.mbarrier::complete_tx::bytes [%0], [%1], %2, [%3];" \
        :: "r"((uint32_t)(dst)), "l"(src), "r"((uint32_t)(bytes)), "r"((uint32_t)(mb)) : "memory")
#define BULK_S2G(gdst, ssrc, bytes) \
    asm volatile("cp.async.bulk.global.shared::cta.bulk_group [%0], [%1], %2;" \
        :: "l"(gdst), "r"((uint32_t)(ssrc)), "r"((uint32_t)(bytes)) : "memory")
#define FENCE_ASYNC() asm volatile("fence.proxy.async.shared::cta;" ::: "memory")

__device__ __forceinline__ void mbar_wait(uint32_t mb, uint32_t parity) {
    uint32_t done;
    asm volatile(
        "{ .reg .pred p; mbarrier.try_wait.parity.acquire.cta.shared::cta.b64 p, [%1], %2; selp.b32 %0, 1, 0, p; }"
        : "=r"(done) : "r"(mb), "r"(parity) : "memory");
    if (!done) {
        asm volatile(
            "{ .reg .pred P1;\n"
            "W%=: mbarrier.try_wait.parity.acquire.cta.shared::cta.b64 P1, [%0], %1, 0x989680;\n"
            "@P1 bra.uni D%=;\n bra.uni W%=;\n D%=: }"
            :: "r"(mb), "r"(parity) : "memory");
    }
}

__device__ __forceinline__ void mma_f16_ss(uint32_t d, uint64_t a, uint64_t b,
                                           uint32_t idesc, uint32_t en) {
#if TC_ENABLED
    asm volatile(
        "{ .reg .pred p; setp.ne.u32 p, %4, 0;\n"
        "tcgen05.mma.cta_group::1.kind::f16 [%0], %1, %2, %3, {%5,%5,%5,%5}, p; }"
        :: "r"(d), "l"(a), "l"(b), "r"(idesc), "r"(en), "r"(0u) : "memory");
#endif
}

__device__ __forceinline__ void tc_ld_x32(uint32_t* r, uint32_t addr) {
#if TC_ENABLED
    asm volatile("tcgen05.ld.sync.aligned.32x32b.x32.b32 "
        "{%0,%1,%2,%3,%4,%5,%6,%7,%8,%9,%10,%11,%12,%13,%14,%15,"
        "%16,%17,%18,%19,%20,%21,%22,%23,%24,%25,%26,%27,%28,%29,%30,%31}, [%32];"
        : "=r"(r[0]),"=r"(r[1]),"=r"(r[2]),"=r"(r[3]),"=r"(r[4]),"=r"(r[5]),"=r"(r[6]),"=r"(r[7]),
          "=r"(r[8]),"=r"(r[9]),"=r"(r[10]),"=r"(r[11]),"=r"(r[12]),"=r"(r[13]),"=r"(r[14]),"=r"(r[15]),
          "=r"(r[16]),"=r"(r[17]),"=r"(r[18]),"=r"(r[19]),"=r"(r[20]),"=r"(r[21]),"=r"(r[22]),"=r"(r[23]),
          "=r"(r[24]),"=r"(r[25]),"=r"(r[26]),"=r"(r[27]),"=r"(r[28]),"=r"(r[29]),"=r"(r[30]),"=r"(r[31])
        : "r"(addr));
#endif
}

// ---------------------------------------------------------------------------
// Kernel 1: KNN (k=8), 2 threads/point, min-of-4 batched scan, smem merge,
// gather/mean + direct packed x emission. Distance drops the per-point tsq
// constant (top-k invariant); worst-slot recompute seeds with -FLT_MAX since
// d2' can be negative.
// ---------------------------------------------------------------------------
#define PPB 256
#define NTH 512
#define SCH 2048

__device__ __forceinline__ void heap_insert(
    float d2, int idx, float bd[KNN], int bi[KNN], float& wmax, int& wslot)
{
#pragma unroll
    for (int i = 0; i < KNN; i++)
        if (i == wslot) { bd[i] = d2; bi[i] = idx; }
    float wm = -3.4e38f; int ws = 0;
#pragma unroll
    for (int i = 0; i < KNN; i++)
        if (bd[i] > wm) { wm = bd[i]; ws = i; }
    wmax = wm; wslot = ws;
}

__global__ void __launch_bounds__(NTH) knn_build_xpk(
    const float* __restrict__ tmpl, const float* __restrict__ surf,
    const float* __restrict__ pfeat)
{
    __shared__ float4 ssurf[SCH];
    __shared__ int    sidx[PPB * KNN];
    __shared__ float  sdB[PPB * KNN];
    __shared__ int    siB[PPB * KNN];

    const int b  = blockIdx.x / (TT / PPB);
    const int p0 = (blockIdx.x % (TT / PPB)) * PPB;
    const int tid = threadIdx.x;
    const int pl  = tid & (PPB - 1);
    const int half = tid >> 8;

    const int pt = p0 + pl;
    const size_t trow = ((size_t)b * TT + pt) * 3;
    const float tx = tmpl[trow + 0], ty = tmpl[trow + 1], tz = tmpl[trow + 2];
    const float ntx = -2.f * tx, nty = -2.f * ty, ntz = -2.f * tz;

    float bd[KNN]; int bi[KNN];
#pragma unroll
    for (int i = 0; i < KNN; i++) { bd[i] = 3.4e38f; bi[i] = 0; }
    float wmax = 3.4e38f; int wslot = 0;

    for (int c0 = 0; c0 < SSZ; c0 += SCH) {
        __syncthreads();
        for (int i = tid; i < SCH; i += NTH) {
            size_t srow = ((size_t)b * SSZ + c0 + i) * 3;
            float sx = surf[srow], sy = surf[srow + 1], sz = surf[srow + 2];
            ssurf[i] = make_float4(sx, sy, sz, sx * sx + sy * sy + sz * sz);
        }
        __syncthreads();
        const int sbeg = half * (SCH / 2);
        // min-of-4 batched scan; d2' = s_sq - 2*dot (tsq dropped)
        for (int s = sbeg; s < sbeg + SCH / 2; s += 4) {
            float4 v0 = ssurf[s + 0], v1 = ssurf[s + 1];
            float4 v2 = ssurf[s + 2], v3 = ssurf[s + 3];
            float e0 = fmaf(ntx, v0.x, fmaf(nty, v0.y, fmaf(ntz, v0.z, v0.w)));
            float e1 = fmaf(ntx, v1.x, fmaf(nty, v1.y, fmaf(ntz, v1.z, v1.w)));
            float e2 = fmaf(ntx, v2.x, fmaf(nty, v2.y, fmaf(ntz, v2.z, v2.w)));
            float e3 = fmaf(ntx, v3.x, fmaf(nty, v3.y, fmaf(ntz, v3.z, v3.w)));
            float m = fminf(fminf(e0, e1), fminf(e2, e3));
            if (m < wmax) {
                if (e0 < wmax) heap_insert(e0, c0 + s + 0, bd, bi, wmax, wslot);
                if (e1 < wmax) heap_insert(e1, c0 + s + 1, bd, bi, wmax, wslot);
                if (e2 < wmax) heap_insert(e2, c0 + s + 2, bd, bi, wmax, wslot);
                if (e3 < wmax) heap_insert(e3, c0 + s + 3, bd, bi, wmax, wslot);
            }
        }
    }

    // merge: half B publishes, half A folds B's 8 candidates into its heap
    if (half == 1) {
#pragma unroll
        for (int i = 0; i < KNN; i++) {
            sdB[pl * KNN + i] = bd[i];
            siB[pl * KNN + i] = bi[i];
        }
    }
    __syncthreads();
    if (half == 0) {
#pragma unroll
        for (int n = 0; n < KNN; n++) {
            float d2 = sdB[pl * KNN + n];
            int   ii = siB[pl * KNN + n];
            if (d2 < wmax) heap_insert(d2, ii, bd, bi, wmax, wslot);
        }
#pragma unroll
        for (int i = 0; i < KNN; i++) sidx[pl * KNN + i] = bi[i];
    }
    __syncthreads();

    // gather + packed emission: 16 warps x 16 points
    const int lane = tid & 31, wid = tid >> 5;
    for (int q = 0; q < PPB / 16; q++) {
        const int lp = wid * (PPB / 16) + q;
        float acc[8];
#pragma unroll
        for (int j = 0; j < 8; j++) acc[j] = 0.f;
#pragma unroll
        for (int n = 0; n < KNN; n++) {
            const int sI = sidx[lp * KNN + n];
            const float4* rowp = (const float4*)(pfeat + ((size_t)b * SSZ + sI) * DD + lane * 8);
            float4 a0 = rowp[0], a1 = rowp[1];
            acc[0] += a0.x; acc[1] += a0.y; acc[2] += a0.z; acc[3] += a0.w;
            acc[4] += a1.x; acc[5] += a1.y; acc[6] += a1.z; acc[7] += a1.w;
        }
        const int row = b * TT + p0 + lp;
        const int tile = row >> 7, rloc = row & 127;
        __align__(16) __nv_bfloat16 h[8], l[8];
#pragma unroll
        for (int j = 0; j < 8; j++) {
            float v = acc[j] * 0.125f;
            h[j] = __float2bfloat16(v);
            l[j] = __float2bfloat16(v - __bfloat162float(h[j]));
        }
        const uint32_t off = SWZ128((uint32_t)(rloc * 128 + ((lane & 7) << 4)));
        const size_t blk = ((size_t)(tile * 5) + (lane >> 3)) * 16384 + off;
        *(uint4*)((char*)g_xh + blk) = *(const uint4*)h;
        *(uint4*)((char*)g_xl + blk) = *(const uint4*)l;
        if (lane < 3) {
            float v = tmpl[(size_t)row * 3 + lane];
            __nv_bfloat16 hh = __float2bfloat16(v);
            __nv_bfloat16 ll = __float2bfloat16(v - __bfloat162float(hh));
            const uint32_t o2 = SWZ128((uint32_t)(rloc * 128)) + (lane << 1);
            const size_t b2 = ((size_t)(tile * 5) + 4) * 16384 + o2;
            *(__nv_bfloat16*)((char*)g_xh + b2) = hh;
            *(__nv_bfloat16*)((char*)g_xl + b2) = ll;
        }
    }
}

// ---------------------------------------------------------------------------
// prep jobs (layer-1 weights use permuted row map: k'<256 -> k'+3; 256..258 -> k'-256)
// ---------------------------------------------------------------------------
__device__ __forceinline__ void pack_w1_elem(
    const float* W, __nv_bfloat16* hi, __nv_bfloat16* lo, int idx, int N)
{
    int n = idx / 320, kp = idx - n * 320;
    float v;
    if (kp < 256)       v = W[(size_t)(kp + 3) * N + n];
    else if (kp < 259)  v = W[(size_t)(kp - 256) * N + n];
    else                v = 0.f;
    __nv_bfloat16 h = __float2bfloat16(v);
    int ch = kp >> 6, kc = kp & 63;
    uint32_t e = (uint32_t)ch * (N * 64) + (SWZ128((uint32_t)(n * 128 + kc * 2)) >> 1);
    hi[e] = h;
    lo[e] = __float2bfloat16(v - __bfloat162float(h));
}

__device__ __forceinline__ void pack_w_elem(
    const float* W, __nv_bfloat16* hi, __nv_bfloat16* lo,
    int idx, int N, int Kpad)
{
    int n = idx / Kpad, k = idx - n * Kpad;
    float v = W[(size_t)k * N + n];
    __nv_bfloat16 h = __float2bfloat16(v);
    int ch = k >> 6, kc = k & 63;
    uint32_t e = (uint32_t)ch * (N * 64) + (SWZ128((uint32_t)(n * 128 + kc * 2)) >> 1);
    hi[e] = h;
    lo[e] = __float2bfloat16(v - __bfloat162float(h));
}

__global__ void __launch_bounds__(256) prep_job(
    int job,
    const float* __restrict__ W, const float* __restrict__ bias_in,
    const float* __restrict__ gfeat)
{
    const int bid = blockIdx.x, tid = threadIdx.x;
    if (job == 0) {
        pack_w1_elem(W, g_dw1h, g_dw1l, bid * 256 + tid, 256);
    } else if (job == 1) {
        pack_w_elem(W, g_dw2h, g_dw2l, bid * 256 + tid, 256, 256);
    } else if (job == 2) {
        pack_w1_elem(W, g_mw1h, g_mw1l, bid * 256 + tid, 128);
    } else if (job == 3) {
        pack_w_elem(W, g_mw2h, g_mw2l, bid * 256 + tid, 64, 128);
    } else {
        int b = bid;
        float s = bias_in[tid];
#pragma unroll 4
        for (int k = 0; k < GG; k++)
            s = fmaf(gfeat[b * GG + k], W[(size_t)(KX + k) * 256 + tid], s);
        g_gbd[b * 256 + tid] = s;
    }
}

__global__ void __launch_bounds__(256) prep_gbm(
    const float* __restrict__ mw1, const float* __restrict__ mb1,
    const float* __restrict__ gfeat)
{
    const int b = blockIdx.x, tid = threadIdx.x;
    if (tid < 128) {
        float s = mb1[tid];
#pragma unroll 4
        for (int k = 0; k < GG; k++)
            s = fmaf(gfeat[b * GG + k], mw1[(size_t)(KX + k) * 128 + tid], s);
        g_gbm[b * 128 + tid] = s;
    }
}

// ---------------------------------------------------------------------------
// tcgen05 GEMM with fused epilogue (round-14 proven version).
// ---------------------------------------------------------------------------
#define OUT_PACK 0
#define OUT_DISP 1
#define OUT_MAT  2

template<int NT, int OMODE>
__global__ void __launch_bounds__(128) gemm_tc3(
    const __nv_bfloat16* __restrict__ Ah, const __nv_bfloat16* __restrict__ Al, int nch,
    const __nv_bfloat16* __restrict__ Bh, const __nv_bfloat16* __restrict__ Bl,
    const float* __restrict__ bias, int bstride,
    __nv_bfloat16* __restrict__ Oh, __nv_bfloat16* __restrict__ Ol,
    const float* __restrict__ w3, const float* __restrict__ b3,
    float* __restrict__ out)
{
#if TC_ENABLED
    extern __shared__ __align__(1024) char smem[];
    constexpr uint32_t B_OFF = 32768u;
    constexpr uint32_t STAGE = 32768u + NT * 256u;
    constexpr int SWN = (OMODE == OUT_DISP) ? 768 : ((OMODE == OUT_MAT) ? 64 : 1);
    __shared__ uint32_t s_tmem;
    __shared__ __align__(8) uint64_t s_mb[4];
    __shared__ float sb[NT];
    __shared__ float sw[SWN];

    const uint32_t smb  = smem_u32(smem);
    const uint32_t mbb  = smem_u32(&s_mb[0]);
    const int tid = threadIdx.x, wid = tid >> 5, lane = tid & 31;
    const int tile = blockIdx.x, bm = tile * 128;

    for (int i = tid; i < NT; i += 128) sb[i] = bias[(bm >> 14) * bstride + i];
    if (OMODE != OUT_PACK)
        for (int i = tid; i < SWN; i += 128) sw[i] = w3[i];
    if (wid == 0) { TC_ALLOC(smem_u32(&s_tmem), NT); TC_RELINQ(); }
    if (tid == 0)
        for (int i = 0; i < 4; i++) MBAR_INIT(mbb + i * 8, 1);
    __syncthreads();
    uint32_t tmem;
    asm volatile("ld.shared.b32 %0, [%1];" : "=r"(tmem) : "r"(smem_u32(&s_tmem)));

    const uint32_t idesc = (1u << 4) | (1u << 7) | (1u << 10) | ((NT / 8) << 17) | (8u << 24);

    if (wid == 0) {
        uint32_t pd[2] = {0u, 0u}, pm[2] = {0u, 0u};
        const uint32_t ep = elect_one_pred();

        if (ep) {
            for (int c = 0; c < 2 && c < nch; c++) {
                const int s = c & 1;
                const uint32_t st = smb + s * STAGE;
                MBAR_EXPECT_TX(mbb + s * 8, STAGE);
                BULK_G2S(st,                    Ah + ((size_t)tile * nch + c) * 8192, 16384, mbb + s * 8);
                BULK_G2S(st + 16384,            Al + ((size_t)tile * nch + c) * 8192, 16384, mbb + s * 8);
                BULK_G2S(st + B_OFF,            Bh + (size_t)c * NT * 64, NT * 128, mbb + s * 8);
                BULK_G2S(st + B_OFF + NT * 128, Bl + (size_t)c * NT * 64, NT * 128, mbb + s * 8);
            }
        }
        for (int ch = 0; ch < nch; ch++) {
            const int s = ch & 1;
            const uint32_t st = smb + s * STAGE;
            mbar_wait(mbb + s * 8, pd[s]); pd[s] ^= 1;
            if (ep) {
                uint64_t ah = MAKE_DESC(st), al = MAKE_DESC(st + 16384);
                uint64_t bh = MAKE_DESC(st + B_OFF), bl = MAKE_DESC(st + B_OFF + NT * 128);
#pragma unroll
                for (int ks = 0; ks < 4; ks++) {
                    uint32_t en0 = (ch == 0 && ks == 0) ? 0u : 1u;
                    mma_f16_ss(tmem, ah + ks * 2, bh + ks * 2, idesc, en0);
                    mma_f16_ss(tmem, ah + ks * 2, bl + ks * 2, idesc, 1u);
                    mma_f16_ss(tmem, al + ks * 2, bh + ks * 2, idesc, 1u);
                }
                TC_COMMIT(mbb + 16 + s * 8);
            }
            if (ch + 2 < nch) {
                mbar_wait(mbb + 16 + s * 8, pm[s]); pm[s] ^= 1;
                if (ep) {
                    const int c = ch + 2;
                    MBAR_EXPECT_TX(mbb + s * 8, STAGE);
                    BULK_G2S(st,                    Ah + ((size_t)tile * nch + c) * 8192, 16384, mbb + s * 8);
                    BULK_G2S(st + 16384,            Al + ((size_t)tile * nch + c) * 8192, 16384, mbb + s * 8);
                    BULK_G2S(st + B_OFF,            Bh + (size_t)c * NT * 64, NT * 128, mbb + s * 8);
                    BULK_G2S(st + B_OFF + NT * 128, Bl + (size_t)c * NT * 64, NT * 128, mbb + s * 8);
                }
            }
        }
        const int fs = (nch - 1) & 1;
        mbar_wait(mbb + 16 + fs * 8, pm[fs]);
    }
    __syncthreads();
    TC_FENCE_AFTER();

    const int rloc = wid * 32 + lane;
    const size_t row = (size_t)bm + rloc;

    if (OMODE == OUT_PACK) {
        constexpr int NCH2 = NT / 64;
#pragma unroll
        for (int c0 = 0; c0 < NT; c0 += 32) {
            uint32_t r[32];
            tc_ld_x32(r, tmem + c0);
            TC_WAIT_LD();
#pragma unroll
            for (int j4 = 0; j4 < 8; j4++) {
                const int c = c0 + j4 * 4;
                float v0 = fmaxf(__uint_as_float(r[j4 * 4 + 0]) + sb[c + 0], 0.f);
                float v1 = fmaxf(__uint_as_float(r[j4 * 4 + 1]) + sb[c + 1], 0.f);
                float v2 = fmaxf(__uint_as_float(r[j4 * 4 + 2]) + sb[c + 2], 0.f);
                float v3 = fmaxf(__uint_as_float(r[j4 * 4 + 3]) + sb[c + 3], 0.f);
                __align__(8) __nv_bfloat16 hh[4], ll[4];
                hh[0] = __float2bfloat16(v0); ll[0] = __float2bfloat16(v0 - __bfloat162float(hh[0]));
                hh[1] = __float2bfloat16(v1); ll[1] = __float2bfloat16(v1 - __bfloat162float(hh[1]));
                hh[2] = __float2bfloat16(v2); ll[2] = __float2bfloat16(v2 - __bfloat162float(hh[2]));
                hh[3] = __float2bfloat16(v3); ll[3] = __float2bfloat16(v3 - __bfloat162float(hh[3]));
                const int chunk = c >> 6, cc = c & 63;
                uint32_t off = (uint32_t)chunk * 16384u
                             + SWZ128((uint32_t)(rloc * 128 + ((cc >> 3) << 4)))
                             + (uint32_t)((cc & 7) << 1);
                *(uint64_t*)(smem + off)                   = *(const uint64_t*)hh;
                *(uint64_t*)(smem + NCH2 * 16384u + off)   = *(const uint64_t*)ll;
            }
        }
        __syncthreads();
        if (tid == 0) {
            FENCE_ASYNC();
            for (int ch = 0; ch < NCH2; ch++) {
                BULK_S2G(Oh + ((size_t)tile * NCH2 + ch) * 8192, smb + ch * 16384u, 16384);
                BULK_S2G(Ol + ((size_t)tile * NCH2 + ch) * 8192, smb + (NCH2 + ch) * 16384u, 16384);
            }
            asm volatile("cp.async.bulk.commit_group;" ::: "memory");
            asm volatile("cp.async.bulk.wait_group 0;" ::: "memory");
        }
    } else {
        float a0 = 0.f, a1 = 0.f, a2 = 0.f;
#pragma unroll
        for (int c0 = 0; c0 < NT; c0 += 32) {
            uint32_t r[32];
            tc_ld_x32(r, tmem + c0);
            TC_WAIT_LD();
#pragma unroll
            for (int j4 = 0; j4 < 8; j4++) {
                const int c = c0 + j4 * 4;
#pragma unroll
                for (int k = 0; k < 4; k++) {
                    float v = fmaxf(__uint_as_float(r[j4 * 4 + k]) + sb[c + k], 0.f);
                    if (OMODE == OUT_DISP) {
                        a0 = fmaf(v, sw[(c + k) * 3 + 0], a0);
                        a1 = fmaf(v, sw[(c + k) * 3 + 1], a1);
                        a2 = fmaf(v, sw[(c + k) * 3 + 2], a2);
                    } else {
                        a0 = fmaf(v, sw[c + k], a0);
                    }
                }
            }
        }
        if (OMODE == OUT_DISP) {
            out[row * 3 + 0] = a0 + b3[0];
            out[row * 3 + 1] = a1 + b3[1];
            out[row * 3 + 2] = a2 + b3[2];
        } else {
            float z = a0 + b3[0];
            out[row] = 1.f / (1.f + expf(-z));
        }
    }
    __syncthreads();
    if (wid == 0) TC_DEALLOC(tmem, NT);
#endif  // TC_ENABLED
}

// ---------------------------------------------------------------------------
extern "C" void kernel_launch(void* const* d_in, const int* in_sizes, int n_in,
                              void* d_out, int out_size)
{
    const float* tmpl  = (const float*)d_in[0];
    const float* surf  = (const float*)d_in[1];
    const float* gfeat = (const float*)d_in[2];
    const float* pfeat = (const float*)d_in[3];
    const float* dw1 = (const float*)d_in[4];
    const float* db1 = (const float*)d_in[5];
    const float* dw2 = (const float*)d_in[6];
    const float* db2 = (const float*)d_in[7];
    const float* dw3 = (const float*)d_in[8];
    const float* db3 = (const float*)d_in[9];
    const float* mw1 = (const float*)d_in[10];
    const float* mb1 = (const float*)d_in[11];
    const float* mw2 = (const float*)d_in[12];
    const float* mb2 = (const float*)d_in[13];
    const float* mw3 = (const float*)d_in[14];
    const float* mb3 = (const float*)d_in[15];
    float* out = (float*)d_out;

    float *gbd, *gbm;
    cudaGetSymbolAddress((void**)&gbd, g_gbd);
    cudaGetSymbolAddress((void**)&gbm, g_gbm);
    __nv_bfloat16 *xh, *xl, *h1h, *h1l, *m1h, *m1l;
    __nv_bfloat16 *dw1h, *dw1l, *dw2h, *dw2l, *mw1h, *mw1l, *mw2h, *mw2l;
    cudaGetSymbolAddress((void**)&xh,  g_xh);
    cudaGetSymbolAddress((void**)&xl,  g_xl);
    cudaGetSymbolAddress((void**)&h1h, g_h1h);
    cudaGetSymbolAddress((void**)&h1l, g_h1l);
    cudaGetSymbolAddress((void**)&m1h, g_m1h);
    cudaGetSymbolAddress((void**)&m1l, g_m1l);
    cudaGetSymbolAddress((void**)&dw1h, g_dw1h);
    cudaGetSymbolAddress((void**)&dw1l, g_dw1l);
    cudaGetSymbolAddress((void**)&dw2h, g_dw2h);
    cudaGetSymbolAddress((void**)&dw2l, g_dw2l);
    cudaGetSymbolAddress((void**)&mw1h, g_mw1h);
    cudaGetSymbolAddress((void**)&mw1l, g_mw1l);
    cudaGetSymbolAddress((void**)&mw2h, g_mw2h);
    cudaGetSymbolAddress((void**)&mw2l, g_mw2l);

    const int SM1 = 2 * (32768 + 256 * 256);
    const int SM3 = 2 * (32768 + 128 * 256);
    const int SM4 = 2 * (32768 +  64 * 256);
    cudaFuncSetAttribute((const void*)gemm_tc3<256, OUT_PACK>, cudaFuncAttributeMaxDynamicSharedMemorySize, SM1);
    cudaFuncSetAttribute((const void*)gemm_tc3<256, OUT_DISP>, cudaFuncAttributeMaxDynamicSharedMemorySize, SM1);
    cudaFuncSetAttribute((const void*)gemm_tc3<128, OUT_PACK>, cudaFuncAttributeMaxDynamicSharedMemorySize, SM3);
    cudaFuncSetAttribute((const void*)gemm_tc3<64,  OUT_MAT>,  cudaFuncAttributeMaxDynamicSharedMemorySize, SM4);

    static cudaStream_t s1 = nullptr;
    static cudaEvent_t ev0 = nullptr, evP = nullptr, evX = nullptr, evM = nullptr;
    static int forked = -1;
    if (forked < 0) {
        bool ok = cudaStreamCreateWithFlags(&s1, cudaStreamNonBlocking) == cudaSuccess
               && cudaEventCreateWithFlags(&ev0, cudaEventDisableTiming) == cudaSuccess
               && cudaEventCreateWithFlags(&evP, cudaEventDisableTiming) == cudaSuccess
               && cudaEventCreateWithFlags(&evX, cudaEventDisableTiming) == cudaSuccess
               && cudaEventCreateWithFlags(&evM, cudaEventDisableTiming) == cudaSuccess;
        forked = ok ? 1 : 0;
    }

    if (forked == 1) {
        cudaEventRecord(ev0, 0);
        cudaStreamWaitEvent(s1, ev0, 0);
        prep_job<<<320, 256, 0, s1>>>(0, dw1, nullptr, gfeat);
        prep_job<<<256, 256, 0, s1>>>(1, dw2, nullptr, gfeat);
        prep_job<<<160, 256, 0, s1>>>(2, mw1, nullptr, gfeat);
        prep_job<<<32,  256, 0, s1>>>(3, mw2, nullptr, gfeat);
        prep_job<<<4,   256, 0, s1>>>(4, dw1, db1, gfeat);
        prep_gbm<<<4,   256, 0, s1>>>(mw1, mb1, gfeat);
        cudaEventRecord(evP, s1);

        knn_build_xpk<<<MM / PPB, NTH>>>(tmpl, surf, pfeat);
        cudaEventRecord(evX, 0);

        cudaStreamWaitEvent(s1, evX, 0);
        gemm_tc3<128, OUT_PACK><<<NTILE, 128, SM3, s1>>>(
            xh, xl, 5, mw1h, mw1l, gbm, 128, m1h, m1l, nullptr, nullptr, nullptr);
        gemm_tc3<64, OUT_MAT><<<NTILE, 128, SM4, s1>>>(
            m1h, m1l, 2, mw2h, mw2l, mb2, 0, nullptr, nullptr, mw3, mb3, out + (size_t)MM * 3);
        cudaEventRecord(evM, s1);

        cudaStreamWaitEvent(0, evP, 0);
        gemm_tc3<256, OUT_PACK><<<NTILE, 128, SM1>>>(
            xh, xl, 5, dw1h, dw1l, gbd, 256, h1h, h1l, nullptr, nullptr, nullptr);
        gemm_tc3<256, OUT_DISP><<<NTILE, 128, SM1>>>(
            h1h, h1l, 4, dw2h, dw2l, db2, 0, nullptr, nullptr, dw3, db3, out);
        cudaStreamWaitEvent(0, evM, 0);
    } else {
        prep_job<<<320, 256>>>(0, dw1, nullptr, gfeat);
        prep_job<<<256, 256>>>(1, dw2, nullptr, gfeat);
        prep_job<<<160, 256>>>(2, mw1, nullptr, gfeat);
        prep_job<<<32,  256>>>(3, mw2, nullptr, gfeat);
        prep_job<<<4,   256>>>(4, dw1, db1, gfeat);
        prep_gbm<<<4,   256>>>(mw1, mb1, gfeat);
        knn_build_xpk<<<MM / PPB, NTH>>>(tmpl, surf, pfeat);
        gemm_tc3<256, OUT_PACK><<<NTILE, 128, SM1>>>(
            xh, xl, 5, dw1h, dw1l, gbd, 256, h1h, h1l, nullptr, nullptr, nullptr);
        gemm_tc3<128, OUT_PACK><<<NTILE, 128, SM3>>>(
            xh, xl, 5, mw1h, mw1l, gbm, 128, m1h, m1l, nullptr, nullptr, nullptr);
        gemm_tc3<256, OUT_DISP><<<NTILE, 128, SM1>>>(
            h1h, h1l, 4, dw2h, dw2l, db2, 0, nullptr, nullptr, dw3, db3, out);
        gemm_tc3<64, OUT_MAT><<<NTILE, 128, SM4>>>(
            m1h, m1l, 2, mw2h, mw2l, mb2, 0, nullptr, nullptr, mw3, mb3, out + (size_t)MM * 3);
    }
}